// round 6
// baseline (speedup 1.0000x reference)
#include <cuda_runtime.h>
#include <cuda_fp16.h>
#include <cstdint>

#define NW        1024
#define WIN_ELEMS (256*192)
#define LDH       200
#define LDP       264

__device__ __align__(16) __half g_q[NW*WIN_ELEMS];
__device__ __align__(16) __half g_k[NW*WIN_ELEMS];
__device__ __align__(16) __half g_v[NW*WIN_ELEMS];
__device__ __align__(16) __half g_oa[NW*WIN_ELEMS];
__device__ __align__(16) __half g_wh[147456];   // fp16 wqkv (110592) then wout (36864)

__device__ __forceinline__ unsigned smem_u32(const void* ptr)
{
    return (unsigned)__cvta_generic_to_shared(ptr);
}

__device__ __forceinline__ void ldsm4(unsigned* r, unsigned a)
{
    asm volatile("ldmatrix.sync.aligned.m8n8.x4.shared.b16 {%0,%1,%2,%3}, [%4];" : "=r"(r[0]), "=r"(r[1]), "=r"(r[2]), "=r"(r[3]) : "r"(a));
}

__device__ __forceinline__ void ldsm4t(unsigned* r, unsigned a)
{
    asm volatile("ldmatrix.sync.aligned.m8n8.x4.trans.shared.b16 {%0,%1,%2,%3}, [%4];" : "=r"(r[0]), "=r"(r[1]), "=r"(r[2]), "=r"(r[3]) : "r"(a));
}

__device__ __forceinline__ void mma16816(float* d, const unsigned* a, const unsigned* b)
{
    asm volatile("mma.sync.aligned.m16n8k16.row.col.f32.f16.f16.f32 {%0,%1,%2,%3},{%4,%5,%6,%7},{%8,%9},{%0,%1,%2,%3};" : "+f"(d[0]), "+f"(d[1]), "+f"(d[2]), "+f"(d[3]) : "r"(a[0]), "r"(a[1]), "r"(a[2]), "r"(a[3]), "r"(b[0]), "r"(b[1]));
}

// ---------------------------------------------------------------------------
// K0: one-shot weight conversion fp32 -> fp16 (wqkv then wout).
// ---------------------------------------------------------------------------
__global__ __launch_bounds__(256) void convw_kernel(const float* __restrict__ wqkv, const float* __restrict__ wout)
{
    int i = blockIdx.x*256 + threadIdx.x;   // half2 index, 73728 total
    if (i < 55296) {
        ((__half2*)g_wh)[i] = __floats2half2_rn(wqkv[2*i], wqkv[2*i+1]);
    } else if (i < 73728) {
        int j = i - 55296;
        ((__half2*)g_wh)[i] = __floats2half2_rn(wout[2*j], wout[2*j+1]);
    }
}

// ---------------------------------------------------------------------------
// K1: QKV projection (HMMA). One CTA per window (M=256), 512 threads.
// ---------------------------------------------------------------------------
__global__ __launch_bounds__(512) void qkv_kernel(const float* __restrict__ x, const float* __restrict__ bqkv)
{
    extern __shared__ __half sh_qkv[];
    __half* As = sh_qkv;
    __half* Bs = sh_qkv + 256*LDH;

    const int tid  = threadIdx.x;
    const int warp = tid >> 5;
    const int lane = tid & 31;
    const int win  = blockIdx.x;
    const int bb   = win >> 8;
    const int hy   = (win >> 4) & 15;
    const int wx   = win & 15;
    const int winbase = bb*12582912 + hy*786432 + wx*3072;
    const int grp  = lane >> 2;
    const int t2   = (lane & 3) * 2;
    const int wm   = (warp >> 2) * 32;
    const int wn   = (warp & 3) * 48;

    #pragma unroll
    for (int it = 0; it < 24; it++) {
        int i   = tid + it*512;
        int row = i / 48;
        int c   = (i % 48) * 4;
        const float* src = x + winbase + (row>>4)*49152 + (row&15)*192 + c;
        float4 av = *(const float4*)src;
        __half2* dp = (__half2*)(As + row*LDH + c);
        dp[0] = __floats2half2_rn(av.x, av.y);
        dp[1] = __floats2half2_rn(av.z, av.w);
    }

    for (int nt = 0; nt < 3; nt++) {
        __syncthreads();
        const __half* wsrc = g_wh + nt*36864;
        #pragma unroll
        for (int it = 0; it < 9; it++) {
            int i   = tid + it*512;
            int row = i / 24;
            int cc  = (i % 24) * 8;
            *(uint4*)(Bs + row*LDH + cc) = *(const uint4*)(wsrc + row*192 + cc);
        }
        __syncthreads();

        __half* obuf = g_v;
        if (nt == 0) { obuf = g_q; }
        if (nt == 1) { obuf = g_k; }
        const float* bp = bqkv + nt*192;

        for (int mt = 0; mt < 2; mt++) {
            const __half* Am = As + mt*128*LDH;
            float acc[2][6][4];
            for (int i = 0; i < 2; i++) {
                for (int j = 0; j < 6; j++) {
                    for (int q = 0; q < 4; q++) { acc[i][j][q] = 0.f; }
                }
            }

            #pragma unroll
            for (int k0 = 0; k0 < 192; k0 += 16) {
                unsigned afr[2][4];
                #pragma unroll
                for (int mi = 0; mi < 2; mi++) {
                    unsigned aaddr = smem_u32(Am + (wm + mi*16 + (lane&15))*LDH + k0 + (lane>>4)*8);
                    ldsm4(afr[mi], aaddr);
                }
                #pragma unroll
                for (int nj2 = 0; nj2 < 3; nj2++) {
                    unsigned bfr[4];
                    unsigned baddr = smem_u32(Bs + (wn + nj2*16 + (lane&7) + ((lane>>4)<<3))*LDH + k0 + ((lane>>3)&1)*8);
                    ldsm4(bfr, baddr);
                    #pragma unroll
                    for (int mi = 0; mi < 2; mi++) {
                        mma16816(acc[mi][nj2*2],   afr[mi], bfr);
                        mma16816(acc[mi][nj2*2+1], afr[mi], bfr+2);
                    }
                }
            }

            #pragma unroll
            for (int mi = 0; mi < 2; mi++) {
                #pragma unroll
                for (int rh = 0; rh < 2; rh++) {
                    int tok = mt*128 + wm + mi*16 + grp + rh*8;
                    __half* orow = obuf + win*WIN_ELEMS + tok*192;
                    #pragma unroll
                    for (int nj = 0; nj < 6; nj++) {
                        int c = wn + nj*8 + t2;
                        float v0 = acc[mi][nj][rh*2+0] + bp[c];
                        float v1 = acc[mi][nj][rh*2+1] + bp[c+1];
                        *(__half2*)(orow + c) = __floats2half2_rn(v0, v1);
                    }
                }
            }
        }
    }
}

// ---------------------------------------------------------------------------
// K3: fused attention + LePE (HMMA). CTA = half window, 512 threads.
// smem: phase1 Qs[0,51200) Ks[51200,153600)
//       phase2 Ps[0,67584) Vs[67584,169984)
//       phase3 lepe_s[0,49152) (Ps dead), Vs data still valid
//       s_max[169984) s_sum[172032) s_wpe[174080) s_bpe[180992) end 181760
// ---------------------------------------------------------------------------
__global__ __launch_bounds__(512) void attn_kernel(const float* __restrict__ wpe, const float* __restrict__ bpe)
{
    extern __shared__ char sh_attn[];
    __half* Qs     = (__half*)sh_attn;
    __half* Ks     = (__half*)(sh_attn + 51200);
    __half* Ps     = (__half*)sh_attn;
    __half* Vs     = (__half*)(sh_attn + 67584);
    __half* lepe_s = (__half*)sh_attn;
    float*  s_max  = (float*)(sh_attn + 169984);
    float*  s_sum  = (float*)(sh_attn + 172032);
    float*  s_wpe  = (float*)(sh_attn + 174080);
    float*  s_bpe  = (float*)(sh_attn + 180992);

    const int tid  = threadIdx.x;
    const int warp = tid >> 5;
    const int lane = tid & 31;
    const int win  = blockIdx.x >> 1;
    const int t0   = (blockIdx.x & 1) * 128;
    const int grp  = lane >> 2;
    const int t2   = (lane & 3) * 2;

    const __half* qg = g_q + win*WIN_ELEMS + t0*192;
    const __half* kg = g_k + win*WIN_ELEMS;
    const __half* vg = g_v + win*WIN_ELEMS;

    #pragma unroll
    for (int it = 0; it < 4; it++) {
        int i = tid + it*512;
        if (i < 1728) { s_wpe[i] = wpe[i]; }
    }
    if (tid < 192) { s_bpe[tid] = bpe[tid]; }

    #pragma unroll
    for (int it = 0; it < 6; it++) {
        int i   = tid + it*512;
        int row = i / 24;
        int c16 = i % 24;
        *(uint4*)(Qs + row*LDH + c16*8) = *(const uint4*)(qg + row*192 + c16*8);
    }
    #pragma unroll
    for (int it = 0; it < 12; it++) {
        int i   = tid + it*512;
        int row = i / 24;
        int c16 = i % 24;
        *(uint4*)(Ks + row*LDH + c16*8) = *(const uint4*)(kg + row*192 + c16*8);
    }
    __syncthreads();

    // S = Q K^T : warp grid 4M x 4N, warp tile 32x64
    const int swm = (warp >> 2) * 32;
    const int swn = (warp & 3) * 64;
    float acc[2][8][4];
    for (int i = 0; i < 2; i++) {
        for (int j = 0; j < 8; j++) {
            for (int q = 0; q < 4; q++) { acc[i][j][q] = 0.f; }
        }
    }

    #pragma unroll
    for (int k0 = 0; k0 < 192; k0 += 16) {
        unsigned afr[2][4];
        #pragma unroll
        for (int mi = 0; mi < 2; mi++) {
            unsigned aaddr = smem_u32(Qs + (swm + mi*16 + (lane&15))*LDH + k0 + (lane>>4)*8);
            ldsm4(afr[mi], aaddr);
        }
        #pragma unroll
        for (int nj2 = 0; nj2 < 4; nj2++) {
            unsigned bfr[4];
            unsigned baddr = smem_u32(Ks + (swn + nj2*16 + (lane&7) + ((lane>>4)<<3))*LDH + k0 + ((lane>>3)&1)*8);
            ldsm4(bfr, baddr);
            #pragma unroll
            for (int mi = 0; mi < 2; mi++) {
                mma16816(acc[mi][nj2*2],   afr[mi], bfr);
                mma16816(acc[mi][nj2*2+1], afr[mi], bfr+2);
            }
        }
    }

    const float scale = 0.07216878364870323f;
    #pragma unroll
    for (int mi = 0; mi < 2; mi++) {
        #pragma unroll
        for (int nj = 0; nj < 8; nj++) {
            #pragma unroll
            for (int q = 0; q < 4; q++) {
                acc[mi][nj][q] *= scale;
            }
        }
    }

    // per-row max partials
    #pragma unroll
    for (int mi = 0; mi < 2; mi++) {
        #pragma unroll
        for (int rh = 0; rh < 2; rh++) {
            float m = -1e30f;
            #pragma unroll
            for (int nj = 0; nj < 8; nj++) {
                m = fmaxf(m, fmaxf(acc[mi][nj][rh*2], acc[mi][nj][rh*2+1]));
            }
            m = fmaxf(m, __shfl_xor_sync(0xffffffffu, m, 1));
            m = fmaxf(m, __shfl_xor_sync(0xffffffffu, m, 2));
            if ((lane & 3) == 0) {
                s_max[(swm + mi*16 + grp + rh*8)*4 + (warp & 3)] = m;
            }
        }
    }
    __syncthreads();

    // load V (Qs/Ks dead now)
    #pragma unroll
    for (int it = 0; it < 12; it++) {
        int i   = tid + it*512;
        int row = i / 24;
        int c16 = i % 24;
        *(uint4*)(Vs + row*LDH + c16*8) = *(const uint4*)(vg + row*192 + c16*8);
    }

    // exp (unnormalized), store P fp16, per-row sum partials
    #pragma unroll
    for (int mi = 0; mi < 2; mi++) {
        #pragma unroll
        for (int rh = 0; rh < 2; rh++) {
            int row = swm + mi*16 + grp + rh*8;
            float m01 = fmaxf(s_max[row*4+0], s_max[row*4+1]);
            float m23 = fmaxf(s_max[row*4+2], s_max[row*4+3]);
            float rmax = fmaxf(m01, m23);
            float s = 0.f;
            #pragma unroll
            for (int nj = 0; nj < 8; nj++) {
                float e0 = __expf(acc[mi][nj][rh*2+0] - rmax);
                float e1 = __expf(acc[mi][nj][rh*2+1] - rmax);
                s += e0 + e1;
                *(__half2*)(Ps + row*LDP + swn + nj*8 + t2) = __floats2half2_rn(e0, e1);
            }
            s += __shfl_xor_sync(0xffffffffu, s, 1);
            s += __shfl_xor_sync(0xffffffffu, s, 2);
            if ((lane & 3) == 0) {
                s_sum[row*4 + (warp & 3)] = s;
            }
        }
    }
    __syncthreads();

    // O = P V : warp grid 4M x 4N, warp tile 32x48
    const int pwm = (warp >> 2) * 32;
    const int pwn = (warp & 3) * 48;
    float oacc[2][6][4];
    for (int i = 0; i < 2; i++) {
        for (int j = 0; j < 6; j++) {
            for (int q = 0; q < 4; q++) { oacc[i][j][q] = 0.f; }
        }
    }

    #pragma unroll
    for (int k0 = 0; k0 < 256; k0 += 16) {
        unsigned afr[2][4];
        #pragma unroll
        for (int mi = 0; mi < 2; mi++) {
            unsigned aaddr = smem_u32(Ps + (pwm + mi*16 + (lane&15))*LDP + k0 + (lane>>4)*8);
            ldsm4(afr[mi], aaddr);
        }
        #pragma unroll
        for (int nj2 = 0; nj2 < 3; nj2++) {
            unsigned bfr[4];
            unsigned baddr = smem_u32(Vs + (k0 + (lane&7) + ((lane>>3)&1)*8)*LDH + pwn + nj2*16 + (lane>>4)*8);
            ldsm4t(bfr, baddr);
            #pragma unroll
            for (int mi = 0; mi < 2; mi++) {
                mma16816(oacc[mi][nj2*2],   afr[mi], bfr);
                mma16816(oacc[mi][nj2*2+1], afr[mi], bfr+2);
            }
        }
    }
    __syncthreads();   // Ps reads done; safe to overwrite with lepe_s

    // LePE: depthwise 3x3 conv of v reinterpreted as [c][16][16], from Vs smem.
    // Output flat index f = tok*192 + c within window; compute for our 128 tokens.
    #pragma unroll
    for (int it2 = 0; it2 < 48; it2++) {
        int f_loc = tid + it2*512;          // 0..24575
        int f     = t0*192 + f_loc;         // global flat in window
        int c2    = f >> 8;                 // channel image index
        int p     = f & 255;
        int iy    = p >> 4;
        int ix    = p & 15;
        float s = s_bpe[c2];
        #pragma unroll
        for (int dy = -1; dy <= 1; dy++) {
            #pragma unroll
            for (int dx = -1; dx <= 1; dx++) {
                int jy = iy + dy;
                int jx = ix + dx;
                if (jy >= 0 && jy < 16 && jx >= 0 && jx < 16) {
                    int fp = f + dy*16 + dx;
                    unsigned uf = (unsigned)fp;
                    unsigned tokp = uf / 192u;
                    unsigned chp  = uf % 192u;
                    float vv = __half2float(Vs[tokp*LDH + chp]);
                    s += vv * s_wpe[c2*9 + (dy+1)*3 + (dx+1)];
                }
            }
        }
        lepe_s[f_loc] = __float2half(s);
    }
    __syncthreads();

    // epilogue: normalize by rowsum, add lepe, write half
    __half* ow = g_oa + win*WIN_ELEMS;
    #pragma unroll
    for (int mi = 0; mi < 2; mi++) {
        #pragma unroll
        for (int rh = 0; rh < 2; rh++) {
            int rl = pwm + mi*16 + grp + rh*8;
            float tot = s_sum[rl*4+0] + s_sum[rl*4+1] + s_sum[rl*4+2] + s_sum[rl*4+3];
            float inv = 1.f / tot;
            int tok = t0 + rl;
            #pragma unroll
            for (int nj = 0; nj < 6; nj++) {
                int c = pwn + nj*8 + t2;
                __half2 lh = *(const __half2*)(lepe_s + rl*192 + c);
                float2 lp = __half22float2(lh);
                float v0 = oacc[mi][nj][rh*2+0]*inv + lp.x;
                float v1 = oacc[mi][nj][rh*2+1]*inv + lp.y;
                *(__half2*)(ow + tok*192 + c) = __floats2half2_rn(v0, v1);
            }
        }
    }
}

// ---------------------------------------------------------------------------
// K4: output projection (HMMA) + reverse-window scatter. 512 threads.
// ---------------------------------------------------------------------------
__global__ __launch_bounds__(512) void proj_kernel(const float* __restrict__ bout, float* __restrict__ out)
{
    extern __shared__ __half sh_prj[];
    __half* As = sh_prj;
    __half* Bs = sh_prj + 256*LDH;

    const int tid  = threadIdx.x;
    const int warp = tid >> 5;
    const int lane = tid & 31;
    const int m0   = blockIdx.x * 256;
    const int grp  = lane >> 2;
    const int t2   = (lane & 3) * 2;
    const int wm   = (warp >> 2) * 32;
    const int wn   = (warp & 3) * 48;

    #pragma unroll
    for (int it = 0; it < 12; it++) {
        int i   = tid + it*512;
        int row = i / 24;
        int c16 = i % 24;
        *(uint4*)(As + row*LDH + c16*8) = *(const uint4*)(g_oa + (m0+row)*192 + c16*8);
    }
    const __half* wsrc = g_wh + 110592;
    #pragma unroll
    for (int it = 0; it < 9; it++) {
        int i   = tid + it*512;
        int row = i / 24;
        int cc  = (i % 24) * 8;
        *(uint4*)(Bs + row*LDH + cc) = *(const uint4*)(wsrc + row*192 + cc);
    }
    __syncthreads();

    for (int mt = 0; mt < 2; mt++) {
        const __half* Am = As + mt*128*LDH;
        float acc[2][6][4];
        for (int i = 0; i < 2; i++) {
            for (int j = 0; j < 6; j++) {
                for (int q = 0; q < 4; q++) { acc[i][j][q] = 0.f; }
            }
        }

        #pragma unroll
        for (int k0 = 0; k0 < 192; k0 += 16) {
            unsigned afr[2][4];
            #pragma unroll
            for (int mi = 0; mi < 2; mi++) {
                unsigned aaddr = smem_u32(Am + (wm + mi*16 + (lane&15))*LDH + k0 + (lane>>4)*8);
                ldsm4(afr[mi], aaddr);
            }
            #pragma unroll
            for (int nj2 = 0; nj2 < 3; nj2++) {
                unsigned bfr[4];
                unsigned baddr = smem_u32(Bs + (wn + nj2*16 + (lane&7) + ((lane>>4)<<3))*LDH + k0 + ((lane>>3)&1)*8);
                ldsm4(bfr, baddr);
                #pragma unroll
                for (int mi = 0; mi < 2; mi++) {
                    mma16816(acc[mi][nj2*2],   afr[mi], bfr);
                    mma16816(acc[mi][nj2*2+1], afr[mi], bfr+2);
                }
            }
        }

        #pragma unroll
        for (int mi = 0; mi < 2; mi++) {
            #pragma unroll
            for (int rh = 0; rh < 2; rh++) {
                int m  = m0 + mt*128 + wm + mi*16 + grp + rh*8;
                int wi = m >> 8;
                int t  = m & 255;
                int bb = wi >> 8;
                int hy = (wi >> 4) & 15;
                int wx = wi & 15;
                int ty = t >> 4;
                int tx = t & 15;
                int base = bb*12582912 + hy*786432 + ty*49152 + wx*3072 + tx*192;
                #pragma unroll
                for (int nj = 0; nj < 6; nj++) {
                    int c = wn + nj*8 + t2;
                    float2 o2;
                    o2.x = acc[mi][nj][rh*2+0] + bout[c];
                    o2.y = acc[mi][nj][rh*2+1] + bout[c+1];
                    *(float2*)(out + base + c) = o2;
                }
            }
        }
    }
}

// ---------------------------------------------------------------------------
extern "C" void kernel_launch(void* const* d_in, const int* in_sizes, int n_in,
                              void* d_out, int out_size)
{
    const float* x    = (const float*)d_in[0];
    const float* wqkv = (const float*)d_in[1];
    const float* bqkv = (const float*)d_in[2];
    const float* wpe  = (const float*)d_in[3];
    const float* bpe  = (const float*)d_in[4];
    const float* wout = (const float*)d_in[5];
    const float* bout = (const float*)d_in[6];
    float* out = (float*)d_out;

    const int sm_gemm = (256 + 192) * LDH * 2;   // 179200
    const int sm_attn = 181760;
    cudaFuncSetAttribute(qkv_kernel,  cudaFuncAttributeMaxDynamicSharedMemorySize, sm_gemm);
    cudaFuncSetAttribute(proj_kernel, cudaFuncAttributeMaxDynamicSharedMemorySize, sm_gemm);
    cudaFuncSetAttribute(attn_kernel, cudaFuncAttributeMaxDynamicSharedMemorySize, sm_attn);

    convw_kernel<<<288, 256>>>(wqkv, wout);
    qkv_kernel <<<1024, 512, sm_gemm>>>(x, bqkv);
    attn_kernel<<<2048, 512, sm_attn>>>(wpe, bpe);
    proj_kernel<<<1024, 512, sm_gemm>>>(bout, out);
}

// round 7
// speedup vs baseline: 1.1481x; 1.1481x over previous
#include <cuda_runtime.h>
#include <cuda_fp16.h>
#include <cstdint>

#define NW        1024
#define WIN_ELEMS (256*192)
#define LDH       200
#define LDP       264

__device__ __align__(16) __half g_q[NW*WIN_ELEMS];
__device__ __align__(16) __half g_k[NW*WIN_ELEMS];
__device__ __align__(16) __half g_v[NW*WIN_ELEMS];
__device__ __align__(16) __half g_lepe[NW*WIN_ELEMS];
__device__ __align__(16) __half g_oa[NW*WIN_ELEMS];
__device__ __align__(16) __half g_wh[147456];   // fp16 wqkv (110592) then wout (36864)

__device__ __forceinline__ unsigned smem_u32(const void* ptr)
{
    return (unsigned)__cvta_generic_to_shared(ptr);
}

__device__ __forceinline__ void ldsm4(unsigned* r, unsigned a)
{
    asm volatile("ldmatrix.sync.aligned.m8n8.x4.shared.b16 {%0,%1,%2,%3}, [%4];" : "=r"(r[0]), "=r"(r[1]), "=r"(r[2]), "=r"(r[3]) : "r"(a));
}

__device__ __forceinline__ void ldsm4t(unsigned* r, unsigned a)
{
    asm volatile("ldmatrix.sync.aligned.m8n8.x4.trans.shared.b16 {%0,%1,%2,%3}, [%4];" : "=r"(r[0]), "=r"(r[1]), "=r"(r[2]), "=r"(r[3]) : "r"(a));
}

__device__ __forceinline__ void mma16816(float* d, const unsigned* a, const unsigned* b)
{
    asm volatile("mma.sync.aligned.m16n8k16.row.col.f32.f16.f16.f32 {%0,%1,%2,%3},{%4,%5,%6,%7},{%8,%9},{%0,%1,%2,%3};" : "+f"(d[0]), "+f"(d[1]), "+f"(d[2]), "+f"(d[3]) : "r"(a[0]), "r"(a[1]), "r"(a[2]), "r"(a[3]), "r"(b[0]), "r"(b[1]));
}

// ---------------------------------------------------------------------------
// K0: one-shot weight conversion fp32 -> fp16 (wqkv then wout).
// ---------------------------------------------------------------------------
__global__ __launch_bounds__(256) void convw_kernel(const float* __restrict__ wqkv, const float* __restrict__ wout)
{
    int i = blockIdx.x*256 + threadIdx.x;
    if (i < 55296) {
        ((__half2*)g_wh)[i] = __floats2half2_rn(wqkv[2*i], wqkv[2*i+1]);
    } else if (i < 73728) {
        int j = i - 55296;
        ((__half2*)g_wh)[i] = __floats2half2_rn(wout[2*j], wout[2*j+1]);
    }
}

// ---------------------------------------------------------------------------
// K1: QKV projection (HMMA) + fused LePE tail. CTA = half window (128 rows).
// smem: As 128xLDH (51200) | Bs 96xLDH (38400) | wpe 3456 | bpe 384 = 93440 B
// Warp grid 8M x 2N (tile 16x48); 6 N-tiles of 96 over the 576 outputs.
// LePE: CTA flat v range == channel images [cbase, cbase+96) exactly.
// ---------------------------------------------------------------------------
__global__ __launch_bounds__(512) void qkv_kernel(const float* __restrict__ x, const float* __restrict__ bqkv,
                                                  const float* __restrict__ wpe, const float* __restrict__ bpe)
{
    extern __shared__ __half sh_qkv[];
    __half* As    = sh_qkv;                                // [128][LDH]
    __half* Bs    = sh_qkv + 128*LDH;                      // [96][LDH]
    float*  s_wpe = (float*)(sh_qkv + 128*LDH + 96*LDH);   // 864 floats
    float*  s_bpe = s_wpe + 864;                           // 96 floats

    const int tid  = threadIdx.x;
    const int warp = tid >> 5;
    const int lane = tid & 31;
    const int hw   = blockIdx.x;
    const int win  = hw >> 1;
    const int t0   = (hw & 1) * 128;
    const int cbase= (hw & 1) * 96;
    const int bb   = win >> 8;
    const int hy   = (win >> 4) & 15;
    const int wx   = win & 15;
    const int winbase = bb*12582912 + hy*786432 + wx*3072;
    const int grp  = lane >> 2;
    const int t2   = (lane & 3) * 2;
    const int wm   = (warp >> 1) * 16;
    const int wn   = (warp & 1) * 48;

    // lepe weights for this CTA's 96 channel images
    #pragma unroll
    for (int it = 0; it < 2; it++) {
        int i = tid + it*512;
        if (i < 864) { s_wpe[i] = wpe[cbase*9 + i]; }
    }
    if (tid < 96) { s_bpe[tid] = bpe[cbase + tid]; }

    // gather + fp16 convert A (128 tokens x 192 ch)
    #pragma unroll
    for (int it = 0; it < 12; it++) {
        int i   = tid + it*512;
        int row = i / 48;
        int c   = (i % 48) * 4;
        int gtok = t0 + row;
        const float* src = x + winbase + (gtok>>4)*49152 + (gtok&15)*192 + c;
        float4 av = *(const float4*)src;
        __half2* dp = (__half2*)(As + row*LDH + c);
        dp[0] = __floats2half2_rn(av.x, av.y);
        dp[1] = __floats2half2_rn(av.z, av.w);
    }

    for (int nt = 0; nt < 6; nt++) {
        __syncthreads();
        const __half* wsrc = g_wh + nt*96*192;
        for (int i = tid; i < 2304; i += 512) {
            int row = i / 24;
            int cc  = (i % 24) * 8;
            *(uint4*)(Bs + row*LDH + cc) = *(const uint4*)(wsrc + row*192 + cc);
        }
        __syncthreads();

        __half* obuf = g_v;
        if (nt < 2) { obuf = g_q; }
        else if (nt < 4) { obuf = g_k; }
        const int c0 = (nt & 1) * 96;
        const float* bp = bqkv + nt*96;

        float acc[6][4];
        for (int j = 0; j < 6; j++) {
            for (int q = 0; q < 4; q++) { acc[j][q] = 0.f; }
        }

        #pragma unroll
        for (int k0 = 0; k0 < 192; k0 += 16) {
            unsigned afr[4];
            unsigned aaddr = smem_u32(As + (wm + (lane&15))*LDH + k0 + (lane>>4)*8);
            ldsm4(afr, aaddr);
            #pragma unroll
            for (int nj2 = 0; nj2 < 3; nj2++) {
                unsigned bfr[4];
                unsigned baddr = smem_u32(Bs + (wn + nj2*16 + (lane&7) + ((lane>>4)<<3))*LDH + k0 + ((lane>>3)&1)*8);
                ldsm4(bfr, baddr);
                mma16816(acc[nj2*2],   afr, bfr);
                mma16816(acc[nj2*2+1], afr, bfr+2);
            }
        }

        #pragma unroll
        for (int rh = 0; rh < 2; rh++) {
            int tok = t0 + wm + grp + rh*8;
            __half* orow = obuf + win*WIN_ELEMS + tok*192 + c0;
            #pragma unroll
            for (int nj = 0; nj < 6; nj++) {
                int cl = wn + nj*8 + t2;
                float v0 = acc[nj][rh*2+0] + bp[cl];
                float v1 = acc[nj][rh*2+1] + bp[cl+1];
                *(__half2*)(orow + cl) = __floats2half2_rn(v0, v1);
            }
        }
    }

    // ---- fused LePE: conv3x3 on this CTA's 96 flat channel images ----
    __syncthreads();
    __half* vflat = As;   // 24576 halves, overlays dead A buffer
    const __half* vsrc = g_v + win*WIN_ELEMS + t0*192;
    #pragma unroll
    for (int it = 0; it < 6; it++) {
        int i = tid + it*512;
        ((uint4*)vflat)[i] = ((const uint4*)vsrc)[i];
    }
    __syncthreads();

    __half* ldst = g_lepe + win*WIN_ELEMS + t0*192;
    #pragma unroll
    for (int it = 0; it < 48; it++) {
        int f  = tid + it*512;          // 0..24575
        int ci = f >> 8;                // local image 0..95
        int p  = f & 255;
        int iy = p >> 4;
        int ix = p & 15;
        float s = s_bpe[ci];
        const float* wv = s_wpe + ci*9;
        const __half* img = vflat + ci*256;
        #pragma unroll
        for (int dy = -1; dy <= 1; dy++) {
            #pragma unroll
            for (int dx = -1; dx <= 1; dx++) {
                int jy = iy + dy;
                int jx = ix + dx;
                if (jy >= 0 && jy < 16 && jx >= 0 && jx < 16) {
                    s += __half2float(img[jy*16 + jx]) * wv[(dy+1)*3 + (dx+1)];
                }
            }
        }
        ldst[f] = __float2half(s);
    }
}

// ---------------------------------------------------------------------------
// K3: fused attention (HMMA). CTA = 128 q rows, 512 threads, 2 CTA/SM.
// K processed in 2 chunks of 128, V in 4 chunks of 64; P overlays dead Q/K.
// smem: Qs[0,51200) Kbuf[51200,102400) ; Ps[0,67584) Vbuf[67584,93184)
//       s_max[102400) s_sum[104448) total 106496 B
// ---------------------------------------------------------------------------
__global__ __launch_bounds__(512) void attn_kernel()
{
    extern __shared__ char sh_attn[];
    __half* Qs    = (__half*)sh_attn;
    __half* Kbuf  = (__half*)(sh_attn + 51200);
    __half* Ps    = (__half*)sh_attn;
    __half* Vbuf  = (__half*)(sh_attn + 67584);
    float*  s_max = (float*)(sh_attn + 102400);
    float*  s_sum = (float*)(sh_attn + 104448);

    const int tid  = threadIdx.x;
    const int warp = tid >> 5;
    const int lane = tid & 31;
    const int win  = blockIdx.x >> 1;
    const int t0   = (blockIdx.x & 1) * 128;
    const int grp  = lane >> 2;
    const int t2   = (lane & 3) * 2;

    const __half* qg = g_q + win*WIN_ELEMS + t0*192;
    const __half* kg = g_k + win*WIN_ELEMS;
    const __half* vg = g_v + win*WIN_ELEMS;

    // load Q
    #pragma unroll
    for (int it = 0; it < 6; it++) {
        int i   = tid + it*512;
        int row = i / 24;
        int c16 = i % 24;
        *(uint4*)(Qs + row*LDH + c16*8) = *(const uint4*)(qg + row*192 + c16*8);
    }

    // S = Q K^T over 2 K chunks; warp grid 4M x 4N per chunk (tile 32x32)
    const int swm   = (warp >> 2) * 32;
    const int snloc = (warp & 3) * 32;
    float acc[2][8][4];
    for (int i = 0; i < 2; i++) {
        for (int j = 0; j < 8; j++) {
            for (int q = 0; q < 4; q++) { acc[i][j][q] = 0.f; }
        }
    }

    for (int kc = 0; kc < 2; kc++) {
        #pragma unroll
        for (int it = 0; it < 6; it++) {
            int i   = tid + it*512;
            int row = i / 24;
            int c16 = i % 24;
            *(uint4*)(Kbuf + row*LDH + c16*8) = *(const uint4*)(kg + (kc*128+row)*192 + c16*8);
        }
        __syncthreads();

        #pragma unroll
        for (int k0 = 0; k0 < 192; k0 += 16) {
            unsigned afr[2][4];
            #pragma unroll
            for (int mi = 0; mi < 2; mi++) {
                unsigned aaddr = smem_u32(Qs + (swm + mi*16 + (lane&15))*LDH + k0 + (lane>>4)*8);
                ldsm4(afr[mi], aaddr);
            }
            #pragma unroll
            for (int nj2 = 0; nj2 < 2; nj2++) {
                unsigned bfr[4];
                unsigned baddr = smem_u32(Kbuf + (snloc + nj2*16 + (lane&7) + ((lane>>4)<<3))*LDH + k0 + ((lane>>3)&1)*8);
                ldsm4(bfr, baddr);
                #pragma unroll
                for (int mi = 0; mi < 2; mi++) {
                    mma16816(acc[mi][kc*4 + nj2*2],     afr[mi], bfr);
                    mma16816(acc[mi][kc*4 + nj2*2 + 1], afr[mi], bfr+2);
                }
            }
        }
        __syncthreads();
    }

    const float scale = 0.07216878364870323f;
    #pragma unroll
    for (int mi = 0; mi < 2; mi++) {
        #pragma unroll
        for (int nj = 0; nj < 8; nj++) {
            #pragma unroll
            for (int q = 0; q < 4; q++) {
                acc[mi][nj][q] *= scale;
            }
        }
    }

    // per-row max partials (4 n-warps per row)
    #pragma unroll
    for (int mi = 0; mi < 2; mi++) {
        #pragma unroll
        for (int rh = 0; rh < 2; rh++) {
            float m = -1e30f;
            #pragma unroll
            for (int nj = 0; nj < 8; nj++) {
                m = fmaxf(m, fmaxf(acc[mi][nj][rh*2], acc[mi][nj][rh*2+1]));
            }
            m = fmaxf(m, __shfl_xor_sync(0xffffffffu, m, 1));
            m = fmaxf(m, __shfl_xor_sync(0xffffffffu, m, 2));
            if ((lane & 3) == 0) {
                s_max[(swm + mi*16 + grp + rh*8)*4 + (warp & 3)] = m;
            }
        }
    }
    __syncthreads();    // Qs + Kbuf dead; Ps overlays them

    // exp (unnormalized), store P fp16, per-row sum partials
    #pragma unroll
    for (int mi = 0; mi < 2; mi++) {
        #pragma unroll
        for (int rh = 0; rh < 2; rh++) {
            int row = swm + mi*16 + grp + rh*8;
            float m01 = fmaxf(s_max[row*4+0], s_max[row*4+1]);
            float m23 = fmaxf(s_max[row*4+2], s_max[row*4+3]);
            float rmax = fmaxf(m01, m23);
            float s = 0.f;
            #pragma unroll
            for (int nj = 0; nj < 8; nj++) {
                float e0 = __expf(acc[mi][nj][rh*2+0] - rmax);
                float e1 = __expf(acc[mi][nj][rh*2+1] - rmax);
                s += e0 + e1;
                int col = (nj>>2)*128 + snloc + (nj&3)*8 + t2;
                *(__half2*)(Ps + row*LDP + col) = __floats2half2_rn(e0, e1);
            }
            s += __shfl_xor_sync(0xffffffffu, s, 1);
            s += __shfl_xor_sync(0xffffffffu, s, 2);
            if ((lane & 3) == 0) {
                s_sum[row*4 + (warp & 3)] = s;
            }
        }
    }
    __syncthreads();

    // O = P V over 4 V chunks of 64; warp grid 4M x 4N (tile 32x48)
    const int pwm = (warp >> 2) * 32;
    const int pwn = (warp & 3) * 48;
    float oacc[2][6][4];
    for (int i = 0; i < 2; i++) {
        for (int j = 0; j < 6; j++) {
            for (int q = 0; q < 4; q++) { oacc[i][j][q] = 0.f; }
        }
    }

    for (int vc = 0; vc < 4; vc++) {
        #pragma unroll
        for (int it = 0; it < 3; it++) {
            int i   = tid + it*512;
            int row = i / 24;
            int c16 = i % 24;
            *(uint4*)(Vbuf + row*LDH + c16*8) = *(const uint4*)(vg + (vc*64+row)*192 + c16*8);
        }
        __syncthreads();

        #pragma unroll
        for (int k0 = 0; k0 < 64; k0 += 16) {
            unsigned afr[2][4];
            #pragma unroll
            for (int mi = 0; mi < 2; mi++) {
                unsigned aaddr = smem_u32(Ps + (pwm + mi*16 + (lane&15))*LDP + vc*64 + k0 + (lane>>4)*8);
                ldsm4(afr[mi], aaddr);
            }
            #pragma unroll
            for (int nj2 = 0; nj2 < 3; nj2++) {
                unsigned bfr[4];
                unsigned baddr = smem_u32(Vbuf + (k0 + (lane&7) + ((lane>>3)&1)*8)*LDH + pwn + nj2*16 + (lane>>4)*8);
                ldsm4t(bfr, baddr);
                #pragma unroll
                for (int mi = 0; mi < 2; mi++) {
                    mma16816(oacc[mi][nj2*2],   afr[mi], bfr);
                    mma16816(oacc[mi][nj2*2+1], afr[mi], bfr+2);
                }
            }
        }
        __syncthreads();
    }

    // epilogue: normalize, add lepe (fp16 gmem), write g_oa
    const __half* lw = g_lepe + win*WIN_ELEMS + t0*192;
    __half*       ow = g_oa   + win*WIN_ELEMS;
    #pragma unroll
    for (int mi = 0; mi < 2; mi++) {
        #pragma unroll
        for (int rh = 0; rh < 2; rh++) {
            int rl = pwm + mi*16 + grp + rh*8;
            float tot = s_sum[rl*4+0] + s_sum[rl*4+1] + s_sum[rl*4+2] + s_sum[rl*4+3];
            float inv = 1.f / tot;
            int tok = t0 + rl;
            #pragma unroll
            for (int nj = 0; nj < 6; nj++) {
                int c = pwn + nj*8 + t2;
                __half2 lh = *(const __half2*)(lw + rl*192 + c);
                float2 lp = __half22float2(lh);
                float v0 = oacc[mi][nj][rh*2+0]*inv + lp.x;
                float v1 = oacc[mi][nj][rh*2+1]*inv + lp.y;
                *(__half2*)(ow + tok*192 + c) = __floats2half2_rn(v0, v1);
            }
        }
    }
}

// ---------------------------------------------------------------------------
// K4: output projection (HMMA) + reverse-window scatter. CTA = 128 rows.
// smem: As 128xLDH (51200) + Bs 96xLDH (38400) = 89600 B -> 2 CTA/SM.
// ---------------------------------------------------------------------------
__global__ __launch_bounds__(512) void proj_kernel(const float* __restrict__ bout, float* __restrict__ out)
{
    extern __shared__ __half sh_prj[];
    __half* As = sh_prj;
    __half* Bs = sh_prj + 128*LDH;

    const int tid  = threadIdx.x;
    const int warp = tid >> 5;
    const int lane = tid & 31;
    const int m0   = blockIdx.x * 128;
    const int grp  = lane >> 2;
    const int t2   = (lane & 3) * 2;
    const int wm   = (warp >> 1) * 16;
    const int wn   = (warp & 1) * 48;

    #pragma unroll
    for (int it = 0; it < 6; it++) {
        int i   = tid + it*512;
        int row = i / 24;
        int c16 = i % 24;
        *(uint4*)(As + row*LDH + c16*8) = *(const uint4*)(g_oa + (m0+row)*192 + c16*8);
    }

    for (int nt = 0; nt < 2; nt++) {
        __syncthreads();
        const __half* wsrc = g_wh + 110592 + nt*96*192;
        for (int i = tid; i < 2304; i += 512) {
            int row = i / 24;
            int cc  = (i % 24) * 8;
            *(uint4*)(Bs + row*LDH + cc) = *(const uint4*)(wsrc + row*192 + cc);
        }
        __syncthreads();

        float acc[6][4];
        for (int j = 0; j < 6; j++) {
            for (int q = 0; q < 4; q++) { acc[j][q] = 0.f; }
        }

        #pragma unroll
        for (int k0 = 0; k0 < 192; k0 += 16) {
            unsigned afr[4];
            unsigned aaddr = smem_u32(As + (wm + (lane&15))*LDH + k0 + (lane>>4)*8);
            ldsm4(afr, aaddr);
            #pragma unroll
            for (int nj2 = 0; nj2 < 3; nj2++) {
                unsigned bfr[4];
                unsigned baddr = smem_u32(Bs + (wn + nj2*16 + (lane&7) + ((lane>>4)<<3))*LDH + k0 + ((lane>>3)&1)*8);
                ldsm4(bfr, baddr);
                mma16816(acc[nj2*2],   afr, bfr);
                mma16816(acc[nj2*2+1], afr, bfr+2);
            }
        }

        #pragma unroll
        for (int rh = 0; rh < 2; rh++) {
            int m  = m0 + wm + grp + rh*8;
            int wi = m >> 8;
            int t  = m & 255;
            int bb = wi >> 8;
            int hy = (wi >> 4) & 15;
            int wx = wi & 15;
            int ty = t >> 4;
            int tx = t & 15;
            int base = bb*12582912 + hy*786432 + ty*49152 + wx*3072 + tx*192;
            #pragma unroll
            for (int nj = 0; nj < 6; nj++) {
                int c = nt*96 + wn + nj*8 + t2;
                float2 o2;
                o2.x = acc[nj][rh*2+0] + bout[c];
                o2.y = acc[nj][rh*2+1] + bout[c+1];
                *(float2*)(out + base + c) = o2;
            }
        }
    }
}

// ---------------------------------------------------------------------------
extern "C" void kernel_launch(void* const* d_in, const int* in_sizes, int n_in,
                              void* d_out, int out_size)
{
    const float* x    = (const float*)d_in[0];
    const float* wqkv = (const float*)d_in[1];
    const float* bqkv = (const float*)d_in[2];
    const float* wpe  = (const float*)d_in[3];
    const float* bpe  = (const float*)d_in[4];
    const float* wout = (const float*)d_in[5];
    const float* bout = (const float*)d_in[6];
    float* out = (float*)d_out;

    const int sm_qkv  = 128*LDH*2 + 96*LDH*2 + 864*4 + 96*4;   // 93440
    const int sm_attn = 106496;
    const int sm_prj  = 128*LDH*2 + 96*LDH*2;                  // 89600
    cudaFuncSetAttribute(qkv_kernel,  cudaFuncAttributeMaxDynamicSharedMemorySize, sm_qkv);
    cudaFuncSetAttribute(proj_kernel, cudaFuncAttributeMaxDynamicSharedMemorySize, sm_prj);
    cudaFuncSetAttribute(attn_kernel, cudaFuncAttributeMaxDynamicSharedMemorySize, sm_attn);

    convw_kernel<<<288, 256>>>(wqkv, wout);
    qkv_kernel <<<2048, 512, sm_qkv>>>(x, bqkv, wpe, bpe);
    attn_kernel<<<2048, 512, sm_attn>>>();
    proj_kernel<<<2048, 512, sm_prj>>>(bout, out);
}

// round 8
// speedup vs baseline: 1.1905x; 1.0369x over previous
#include <cuda_runtime.h>
#include <cuda_fp16.h>
#include <cstdint>

#define NW        1024
#define WIN_ELEMS (256*192)
#define LDH       200
#define LDP       264

__device__ __align__(16) __half g_q[NW*WIN_ELEMS];
__device__ __align__(16) __half g_k[NW*WIN_ELEMS];
__device__ __align__(16) __half g_v[NW*WIN_ELEMS];
__device__ __align__(16) __half g_lepe[NW*WIN_ELEMS];
__device__ __align__(16) __half g_wh[147456];   // fp16 wqkv (110592) then wout (36864)

__device__ __forceinline__ unsigned smem_u32(const void* ptr)
{
    return (unsigned)__cvta_generic_to_shared(ptr);
}

__device__ __forceinline__ void ldsm4(unsigned* r, unsigned a)
{
    asm volatile("ldmatrix.sync.aligned.m8n8.x4.shared.b16 {%0,%1,%2,%3}, [%4];" : "=r"(r[0]), "=r"(r[1]), "=r"(r[2]), "=r"(r[3]) : "r"(a));
}

__device__ __forceinline__ void ldsm4t(unsigned* r, unsigned a)
{
    asm volatile("ldmatrix.sync.aligned.m8n8.x4.trans.shared.b16 {%0,%1,%2,%3}, [%4];" : "=r"(r[0]), "=r"(r[1]), "=r"(r[2]), "=r"(r[3]) : "r"(a));
}

__device__ __forceinline__ void mma16816(float* d, const unsigned* a, const unsigned* b)
{
    asm volatile("mma.sync.aligned.m16n8k16.row.col.f32.f16.f16.f32 {%0,%1,%2,%3},{%4,%5,%6,%7},{%8,%9},{%0,%1,%2,%3};" : "+f"(d[0]), "+f"(d[1]), "+f"(d[2]), "+f"(d[3]) : "r"(a[0]), "r"(a[1]), "r"(a[2]), "r"(a[3]), "r"(b[0]), "r"(b[1]));
}

// ---------------------------------------------------------------------------
// K0: one-shot weight conversion fp32 -> fp16 (wqkv then wout).
// ---------------------------------------------------------------------------
__global__ __launch_bounds__(256) void convw_kernel(const float* __restrict__ wqkv, const float* __restrict__ wout)
{
    int i = blockIdx.x*256 + threadIdx.x;
    if (i < 55296) {
        ((__half2*)g_wh)[i] = __floats2half2_rn(wqkv[2*i], wqkv[2*i+1]);
    } else if (i < 73728) {
        int j = i - 55296;
        ((__half2*)g_wh)[i] = __floats2half2_rn(wout[2*j], wout[2*j+1]);
    }
}

// ---------------------------------------------------------------------------
// K1: QKV projection (HMMA) + fused LePE tail. CTA = half window (128 rows).
// ---------------------------------------------------------------------------
__global__ __launch_bounds__(512) void qkv_kernel(const float* __restrict__ x, const float* __restrict__ bqkv,
                                                  const float* __restrict__ wpe, const float* __restrict__ bpe)
{
    extern __shared__ __half sh_qkv[];
    __half* As    = sh_qkv;                                // [128][LDH]
    __half* Bs    = sh_qkv + 128*LDH;                      // [96][LDH]
    float*  s_wpe = (float*)(sh_qkv + 128*LDH + 96*LDH);   // 864 floats
    float*  s_bpe = s_wpe + 864;                           // 96 floats

    const int tid  = threadIdx.x;
    const int warp = tid >> 5;
    const int lane = tid & 31;
    const int hw   = blockIdx.x;
    const int win  = hw >> 1;
    const int t0   = (hw & 1) * 128;
    const int cbase= (hw & 1) * 96;
    const int bb   = win >> 8;
    const int hy   = (win >> 4) & 15;
    const int wx   = win & 15;
    const int winbase = bb*12582912 + hy*786432 + wx*3072;
    const int grp  = lane >> 2;
    const int t2   = (lane & 3) * 2;
    const int wm   = (warp >> 1) * 16;
    const int wn   = (warp & 1) * 48;

    #pragma unroll
    for (int it = 0; it < 2; it++) {
        int i = tid + it*512;
        if (i < 864) { s_wpe[i] = wpe[cbase*9 + i]; }
    }
    if (tid < 96) { s_bpe[tid] = bpe[cbase + tid]; }

    #pragma unroll
    for (int it = 0; it < 12; it++) {
        int i   = tid + it*512;
        int row = i / 48;
        int c   = (i % 48) * 4;
        int gtok = t0 + row;
        const float* src = x + winbase + (gtok>>4)*49152 + (gtok&15)*192 + c;
        float4 av = *(const float4*)src;
        __half2* dp = (__half2*)(As + row*LDH + c);
        dp[0] = __floats2half2_rn(av.x, av.y);
        dp[1] = __floats2half2_rn(av.z, av.w);
    }

    for (int nt = 0; nt < 6; nt++) {
        __syncthreads();
        const __half* wsrc = g_wh + nt*96*192;
        for (int i = tid; i < 2304; i += 512) {
            int row = i / 24;
            int cc  = (i % 24) * 8;
            *(uint4*)(Bs + row*LDH + cc) = *(const uint4*)(wsrc + row*192 + cc);
        }
        __syncthreads();

        __half* obuf = g_v;
        if (nt < 2) { obuf = g_q; }
        else if (nt < 4) { obuf = g_k; }
        const int c0 = (nt & 1) * 96;
        const float* bp = bqkv + nt*96;

        float acc[6][4];
        for (int j = 0; j < 6; j++) {
            for (int q = 0; q < 4; q++) { acc[j][q] = 0.f; }
        }

        #pragma unroll
        for (int k0 = 0; k0 < 192; k0 += 16) {
            unsigned afr[4];
            unsigned aaddr = smem_u32(As + (wm + (lane&15))*LDH + k0 + (lane>>4)*8);
            ldsm4(afr, aaddr);
            #pragma unroll
            for (int nj2 = 0; nj2 < 3; nj2++) {
                unsigned bfr[4];
                unsigned baddr = smem_u32(Bs + (wn + nj2*16 + (lane&7) + ((lane>>4)<<3))*LDH + k0 + ((lane>>3)&1)*8);
                ldsm4(bfr, baddr);
                mma16816(acc[nj2*2],   afr, bfr);
                mma16816(acc[nj2*2+1], afr, bfr+2);
            }
        }

        #pragma unroll
        for (int rh = 0; rh < 2; rh++) {
            int tok = t0 + wm + grp + rh*8;
            __half* orow = obuf + win*WIN_ELEMS + tok*192 + c0;
            #pragma unroll
            for (int nj = 0; nj < 6; nj++) {
                int cl = wn + nj*8 + t2;
                float v0 = acc[nj][rh*2+0] + bp[cl];
                float v1 = acc[nj][rh*2+1] + bp[cl+1];
                *(__half2*)(orow + cl) = __floats2half2_rn(v0, v1);
            }
        }
    }

    // fused LePE: conv3x3 on this CTA's 96 flat channel images
    __syncthreads();
    __half* vflat = As;
    const __half* vsrc = g_v + win*WIN_ELEMS + t0*192;
    #pragma unroll
    for (int it = 0; it < 6; it++) {
        int i = tid + it*512;
        ((uint4*)vflat)[i] = ((const uint4*)vsrc)[i];
    }
    __syncthreads();

    __half* ldst = g_lepe + win*WIN_ELEMS + t0*192;
    #pragma unroll
    for (int it = 0; it < 48; it++) {
        int f  = tid + it*512;
        int ci = f >> 8;
        int p  = f & 255;
        int iy = p >> 4;
        int ix = p & 15;
        float s = s_bpe[ci];
        const float* wv = s_wpe + ci*9;
        const __half* img = vflat + ci*256;
        #pragma unroll
        for (int dy = -1; dy <= 1; dy++) {
            #pragma unroll
            for (int dx = -1; dx <= 1; dx++) {
                int jy = iy + dy;
                int jx = ix + dx;
                if (jy >= 0 && jy < 16 && jx >= 0 && jx < 16) {
                    s += __half2float(img[jy*16 + jx]) * wv[(dy+1)*3 + (dx+1)];
                }
            }
        }
        ldst[f] = __float2half(s);
    }
}

// ---------------------------------------------------------------------------
// K3: fused attention + output projection (HMMA). CTA = 128 q rows, 512 thr.
// smem phases:
//   S:    Qs[0,51200) Kbuf[51200,102400)
//   P/PV: Ps[0,67584) Vbuf[67584,93184)
//   proj: O_s[0,51200) Wt[51200,89600)
//   s_max[102400) s_sum[104448) total 106496 B  -> 2 CTA/SM
// ---------------------------------------------------------------------------
__global__ __launch_bounds__(512) void attn_kernel(const float* __restrict__ bout, float* __restrict__ out)
{
    extern __shared__ char sh_attn[];
    __half* Qs    = (__half*)sh_attn;
    __half* Kbuf  = (__half*)(sh_attn + 51200);
    __half* Ps    = (__half*)sh_attn;
    __half* Vbuf  = (__half*)(sh_attn + 67584);
    __half* O_s   = (__half*)sh_attn;
    __half* Wt    = (__half*)(sh_attn + 51200);
    float*  s_max = (float*)(sh_attn + 102400);
    float*  s_sum = (float*)(sh_attn + 104448);

    const int tid  = threadIdx.x;
    const int warp = tid >> 5;
    const int lane = tid & 31;
    const int win  = blockIdx.x >> 1;
    const int t0   = (blockIdx.x & 1) * 128;
    const int grp  = lane >> 2;
    const int t2   = (lane & 3) * 2;

    const __half* qg = g_q + win*WIN_ELEMS + t0*192;
    const __half* kg = g_k + win*WIN_ELEMS;
    const __half* vg = g_v + win*WIN_ELEMS;

    // load Q
    #pragma unroll
    for (int it = 0; it < 6; it++) {
        int i   = tid + it*512;
        int row = i / 24;
        int c16 = i % 24;
        *(uint4*)(Qs + row*LDH + c16*8) = *(const uint4*)(qg + row*192 + c16*8);
    }

    // ---- S = Q K^T over 2 K chunks; warp grid 4M x 4N (tile 32x32) ----
    const int swm   = (warp >> 2) * 32;
    const int snloc = (warp & 3) * 32;
    float acc[2][8][4];
    for (int i = 0; i < 2; i++) {
        for (int j = 0; j < 8; j++) {
            for (int q = 0; q < 4; q++) { acc[i][j][q] = 0.f; }
        }
    }

    for (int kc = 0; kc < 2; kc++) {
        #pragma unroll
        for (int it = 0; it < 6; it++) {
            int i   = tid + it*512;
            int row = i / 24;
            int c16 = i % 24;
            *(uint4*)(Kbuf + row*LDH + c16*8) = *(const uint4*)(kg + (kc*128+row)*192 + c16*8);
        }
        __syncthreads();

        #pragma unroll
        for (int k0 = 0; k0 < 192; k0 += 16) {
            unsigned afr[2][4];
            #pragma unroll
            for (int mi = 0; mi < 2; mi++) {
                unsigned aaddr = smem_u32(Qs + (swm + mi*16 + (lane&15))*LDH + k0 + (lane>>4)*8);
                ldsm4(afr[mi], aaddr);
            }
            #pragma unroll
            for (int nj2 = 0; nj2 < 2; nj2++) {
                unsigned bfr[4];
                unsigned baddr = smem_u32(Kbuf + (snloc + nj2*16 + (lane&7) + ((lane>>4)<<3))*LDH + k0 + ((lane>>3)&1)*8);
                ldsm4(bfr, baddr);
                #pragma unroll
                for (int mi = 0; mi < 2; mi++) {
                    mma16816(acc[mi][kc*4 + nj2*2],     afr[mi], bfr);
                    mma16816(acc[mi][kc*4 + nj2*2 + 1], afr[mi], bfr+2);
                }
            }
        }
        __syncthreads();
    }

    const float scale = 0.07216878364870323f;
    #pragma unroll
    for (int mi = 0; mi < 2; mi++) {
        #pragma unroll
        for (int nj = 0; nj < 8; nj++) {
            #pragma unroll
            for (int q = 0; q < 4; q++) {
                acc[mi][nj][q] *= scale;
            }
        }
    }

    // per-row max partials
    #pragma unroll
    for (int mi = 0; mi < 2; mi++) {
        #pragma unroll
        for (int rh = 0; rh < 2; rh++) {
            float m = -1e30f;
            #pragma unroll
            for (int nj = 0; nj < 8; nj++) {
                m = fmaxf(m, fmaxf(acc[mi][nj][rh*2], acc[mi][nj][rh*2+1]));
            }
            m = fmaxf(m, __shfl_xor_sync(0xffffffffu, m, 1));
            m = fmaxf(m, __shfl_xor_sync(0xffffffffu, m, 2));
            if ((lane & 3) == 0) {
                s_max[(swm + mi*16 + grp + rh*8)*4 + (warp & 3)] = m;
            }
        }
    }
    __syncthreads();

    // exp (unnormalized) -> Ps, per-row sum partials
    #pragma unroll
    for (int mi = 0; mi < 2; mi++) {
        #pragma unroll
        for (int rh = 0; rh < 2; rh++) {
            int row = swm + mi*16 + grp + rh*8;
            float m01 = fmaxf(s_max[row*4+0], s_max[row*4+1]);
            float m23 = fmaxf(s_max[row*4+2], s_max[row*4+3]);
            float rmax = fmaxf(m01, m23);
            float s = 0.f;
            #pragma unroll
            for (int nj = 0; nj < 8; nj++) {
                float e0 = __expf(acc[mi][nj][rh*2+0] - rmax);
                float e1 = __expf(acc[mi][nj][rh*2+1] - rmax);
                s += e0 + e1;
                int col = (nj>>2)*128 + snloc + (nj&3)*8 + t2;
                *(__half2*)(Ps + row*LDP + col) = __floats2half2_rn(e0, e1);
            }
            s += __shfl_xor_sync(0xffffffffu, s, 1);
            s += __shfl_xor_sync(0xffffffffu, s, 2);
            if ((lane & 3) == 0) {
                s_sum[row*4 + (warp & 3)] = s;
            }
        }
    }
    __syncthreads();

    // ---- O = P V over 4 V chunks of 64; warp grid 4M x 4N (tile 32x48) ----
    const int pwm = (warp >> 2) * 32;
    const int pwn = (warp & 3) * 48;
    float oacc[2][6][4];
    for (int i = 0; i < 2; i++) {
        for (int j = 0; j < 6; j++) {
            for (int q = 0; q < 4; q++) { oacc[i][j][q] = 0.f; }
        }
    }

    for (int vc = 0; vc < 4; vc++) {
        #pragma unroll
        for (int it = 0; it < 3; it++) {
            int i   = tid + it*512;
            int row = i / 24;
            int c16 = i % 24;
            *(uint4*)(Vbuf + row*LDH + c16*8) = *(const uint4*)(vg + (vc*64+row)*192 + c16*8);
        }
        __syncthreads();

        #pragma unroll
        for (int k0 = 0; k0 < 64; k0 += 16) {
            unsigned afr[2][4];
            #pragma unroll
            for (int mi = 0; mi < 2; mi++) {
                unsigned aaddr = smem_u32(Ps + (pwm + mi*16 + (lane&15))*LDP + vc*64 + k0 + (lane>>4)*8);
                ldsm4(afr[mi], aaddr);
            }
            #pragma unroll
            for (int nj2 = 0; nj2 < 3; nj2++) {
                unsigned bfr[4];
                unsigned baddr = smem_u32(Vbuf + (k0 + (lane&7) + ((lane>>3)&1)*8)*LDH + pwn + nj2*16 + (lane>>4)*8);
                ldsm4t(bfr, baddr);
                #pragma unroll
                for (int mi = 0; mi < 2; mi++) {
                    mma16816(oacc[mi][nj2*2],   afr[mi], bfr);
                    mma16816(oacc[mi][nj2*2+1], afr[mi], bfr+2);
                }
            }
        }
        __syncthreads();
    }

    // ---- write O = PV/rowsum + lepe into O_s (fp16, [128][LDH]) ----
    const __half* lw = g_lepe + win*WIN_ELEMS + t0*192;
    #pragma unroll
    for (int mi = 0; mi < 2; mi++) {
        #pragma unroll
        for (int rh = 0; rh < 2; rh++) {
            int rl = pwm + mi*16 + grp + rh*8;
            float tot = s_sum[rl*4+0] + s_sum[rl*4+1] + s_sum[rl*4+2] + s_sum[rl*4+3];
            float inv = 1.f / tot;
            #pragma unroll
            for (int nj = 0; nj < 6; nj++) {
                int c = pwn + nj*8 + t2;
                __half2 lh = *(const __half2*)(lw + rl*192 + c);
                float2 lp = __half22float2(lh);
                float v0 = oacc[mi][nj][rh*2+0]*inv + lp.x;
                float v1 = oacc[mi][nj][rh*2+1]*inv + lp.y;
                *(__half2*)(O_s + rl*LDH + c) = __floats2half2_rn(v0, v1);
            }
        }
    }

    // ---- fused output projection: O_s @ wout, scatter to out ----
    const int jwm = (warp >> 1) * 16;
    const int jwn = (warp & 1) * 48;
    const int bb = win >> 8;
    const int hy = (win >> 4) & 15;
    const int wx = win & 15;

    for (int nt = 0; nt < 2; nt++) {
        __syncthreads();
        const __half* wsrc = g_wh + 110592 + nt*96*192;
        for (int i = tid; i < 2304; i += 512) {
            int row = i / 24;
            int cc  = (i % 24) * 8;
            *(uint4*)(Wt + row*LDH + cc) = *(const uint4*)(wsrc + row*192 + cc);
        }
        __syncthreads();

        float pacc[6][4];
        for (int j = 0; j < 6; j++) {
            for (int q = 0; q < 4; q++) { pacc[j][q] = 0.f; }
        }

        #pragma unroll
        for (int k0 = 0; k0 < 192; k0 += 16) {
            unsigned afr[4];
            unsigned aaddr = smem_u32(O_s + (jwm + (lane&15))*LDH + k0 + (lane>>4)*8);
            ldsm4(afr, aaddr);
            #pragma unroll
            for (int nj2 = 0; nj2 < 3; nj2++) {
                unsigned bfr[4];
                unsigned baddr = smem_u32(Wt + (jwn + nj2*16 + (lane&7) + ((lane>>4)<<3))*LDH + k0 + ((lane>>3)&1)*8);
                ldsm4(bfr, baddr);
                mma16816(pacc[nj2*2],   afr, bfr);
                mma16816(pacc[nj2*2+1], afr, bfr+2);
            }
        }

        #pragma unroll
        for (int rh = 0; rh < 2; rh++) {
            int t  = t0 + jwm + grp + rh*8;   // token within window
            int ty = t >> 4;
            int tx = t & 15;
            int base = bb*12582912 + hy*786432 + ty*49152 + wx*3072 + tx*192;
            #pragma unroll
            for (int nj = 0; nj < 6; nj++) {
                int c = nt*96 + jwn + nj*8 + t2;
                float2 o2;
                o2.x = pacc[nj][rh*2+0] + bout[c];
                o2.y = pacc[nj][rh*2+1] + bout[c+1];
                *(float2*)(out + base + c) = o2;
            }
        }
    }
}

// ---------------------------------------------------------------------------
extern "C" void kernel_launch(void* const* d_in, const int* in_sizes, int n_in,
                              void* d_out, int out_size)
{
    const float* x    = (const float*)d_in[0];
    const float* wqkv = (const float*)d_in[1];
    const float* bqkv = (const float*)d_in[2];
    const float* wpe  = (const float*)d_in[3];
    const float* bpe  = (const float*)d_in[4];
    const float* wout = (const float*)d_in[5];
    const float* bout = (const float*)d_in[6];
    float* out = (float*)d_out;

    const int sm_qkv  = 128*LDH*2 + 96*LDH*2 + 864*4 + 96*4;   // 93440
    const int sm_attn = 106496;
    cudaFuncSetAttribute(qkv_kernel,  cudaFuncAttributeMaxDynamicSharedMemorySize, sm_qkv);
    cudaFuncSetAttribute(attn_kernel, cudaFuncAttributeMaxDynamicSharedMemorySize, sm_attn);

    convw_kernel<<<288, 256>>>(wqkv, wout);
    qkv_kernel <<<2048, 512, sm_qkv>>>(x, bqkv, wpe, bpe);
    attn_kernel<<<2048, 512, sm_attn>>>(bout, out);
}

// round 9
// speedup vs baseline: 1.2589x; 1.0574x over previous
#include <cuda_runtime.h>
#include <cuda_fp16.h>
#include <cstdint>

#define NW        1024
#define WIN_ELEMS (256*192)
#define LDH       200
#define LDP       264

__device__ __align__(16) __half g_q[NW*WIN_ELEMS];
__device__ __align__(16) __half g_k[NW*WIN_ELEMS];
__device__ __align__(16) __half g_v[NW*WIN_ELEMS];
__device__ __align__(16) __half g_lepe[NW*WIN_ELEMS];
__device__ __align__(16) __half g_wh[147456];   // fp16 wqkv (110592) then wout (36864)

__device__ __forceinline__ unsigned smem_u32(const void* ptr)
{
    return (unsigned)__cvta_generic_to_shared(ptr);
}

__device__ __forceinline__ void ldsm4(unsigned* r, unsigned a)
{
    asm volatile("ldmatrix.sync.aligned.m8n8.x4.shared.b16 {%0,%1,%2,%3}, [%4];" : "=r"(r[0]), "=r"(r[1]), "=r"(r[2]), "=r"(r[3]) : "r"(a));
}

__device__ __forceinline__ void ldsm4t(unsigned* r, unsigned a)
{
    asm volatile("ldmatrix.sync.aligned.m8n8.x4.trans.shared.b16 {%0,%1,%2,%3}, [%4];" : "=r"(r[0]), "=r"(r[1]), "=r"(r[2]), "=r"(r[3]) : "r"(a));
}

__device__ __forceinline__ void mma16816(float* d, const unsigned* a, const unsigned* b)
{
    asm volatile("mma.sync.aligned.m16n8k16.row.col.f32.f16.f16.f32 {%0,%1,%2,%3},{%4,%5,%6,%7},{%8,%9},{%0,%1,%2,%3};" : "+f"(d[0]), "+f"(d[1]), "+f"(d[2]), "+f"(d[3]) : "r"(a[0]), "r"(a[1]), "r"(a[2]), "r"(a[3]), "r"(b[0]), "r"(b[1]));
}

__device__ __forceinline__ void cpa16(unsigned dst, const void* src)
{
    asm volatile("cp.async.cg.shared.global [%0], [%1], 16;" :: "r"(dst), "l"(src));
}

#define CPA_COMMIT() asm volatile("cp.async.commit_group;")
#define CPA_WAIT(n)  asm volatile("cp.async.wait_group %0;" :: "n"(n))

// ---------------------------------------------------------------------------
// K0: one-shot weight conversion fp32 -> fp16 (wqkv then wout).
// ---------------------------------------------------------------------------
__global__ __launch_bounds__(256) void convw_kernel(const float* __restrict__ wqkv, const float* __restrict__ wout)
{
    int i = blockIdx.x*256 + threadIdx.x;
    if (i < 55296) {
        ((__half2*)g_wh)[i] = __floats2half2_rn(wqkv[2*i], wqkv[2*i+1]);
    } else if (i < 73728) {
        int j = i - 55296;
        ((__half2*)g_wh)[i] = __floats2half2_rn(wout[2*j], wout[2*j+1]);
    }
}

// ---------------------------------------------------------------------------
// K1: QKV projection (HMMA) + fused LePE tail. CTA = half window (128 rows).
// B tiles: 64 cols, double-buffered via cp.async (9 tiles over 576 outputs).
// smem: As[0,51200) Bs0[51200,76800) Bs1[76800,102400) wpe/bpe[102400,106240)
// Warp grid 8M x 2N (tile 16x32).
// ---------------------------------------------------------------------------
__global__ __launch_bounds__(512) void qkv_kernel(const float* __restrict__ x, const float* __restrict__ bqkv,
                                                  const float* __restrict__ wpe, const float* __restrict__ bpe)
{
    extern __shared__ __half sh_qkv[];
    __half* As    = sh_qkv;                                // [128][LDH]
    float*  s_wpe = (float*)((char*)sh_qkv + 102400);      // 864 floats
    float*  s_bpe = s_wpe + 864;                           // 96 floats

    const int tid  = threadIdx.x;
    const int warp = tid >> 5;
    const int lane = tid & 31;
    const int hw   = blockIdx.x;
    const int win  = hw >> 1;
    const int t0   = (hw & 1) * 128;
    const int cbase= (hw & 1) * 96;
    const int bb   = win >> 8;
    const int hy   = (win >> 4) & 15;
    const int wx   = win & 15;
    const int winbase = bb*12582912 + hy*786432 + wx*3072;
    const int grp  = lane >> 2;
    const int t2   = (lane & 3) * 2;
    const int wm   = (warp >> 1) * 16;
    const int wn   = (warp & 1) * 32;

    // issue B tile 0 and 1 cp.asyncs first (overlap with A gather/convert)
    #pragma unroll
    for (int bt = 0; bt < 2; bt++) {
        const __half* wsrc = g_wh + bt*64*192;
        unsigned bbase = smem_u32((char*)sh_qkv + 51200 + bt*25600);
        #pragma unroll
        for (int it = 0; it < 3; it++) {
            int i   = tid + it*512;
            int row = i / 24;
            int cc  = (i % 24) * 8;
            cpa16(bbase + row*(LDH*2) + cc*2, wsrc + row*192 + cc);
        }
        CPA_COMMIT();
    }

    // lepe params
    #pragma unroll
    for (int it = 0; it < 2; it++) {
        int i = tid + it*512;
        if (i < 864) { s_wpe[i] = wpe[cbase*9 + i]; }
    }
    if (tid < 96) { s_bpe[tid] = bpe[cbase + tid]; }

    // gather + fp16 convert A (128 tokens x 192 ch)
    #pragma unroll
    for (int it = 0; it < 12; it++) {
        int i   = tid + it*512;
        int row = i / 48;
        int c   = (i % 48) * 4;
        int gtok = t0 + row;
        const float* src = x + winbase + (gtok>>4)*49152 + (gtok&15)*192 + c;
        float4 av = *(const float4*)src;
        __half2* dp = (__half2*)(As + row*LDH + c);
        dp[0] = __floats2half2_rn(av.x, av.y);
        dp[1] = __floats2half2_rn(av.z, av.w);
    }

    for (int nt = 0; nt < 9; nt++) {
        if (nt >= 7) { CPA_WAIT(0); } else { CPA_WAIT(1); }
        __syncthreads();

        const __half* Bs = (const __half*)((char*)sh_qkv + 51200 + (nt & 1)*25600);

        float acc[4][4];
        for (int j = 0; j < 4; j++) {
            for (int q = 0; q < 4; q++) { acc[j][q] = 0.f; }
        }

        #pragma unroll
        for (int k0 = 0; k0 < 192; k0 += 16) {
            unsigned afr[4];
            unsigned aaddr = smem_u32(As + (wm + (lane&15))*LDH + k0 + (lane>>4)*8);
            ldsm4(afr, aaddr);
            #pragma unroll
            for (int nj2 = 0; nj2 < 2; nj2++) {
                unsigned bfr[4];
                unsigned baddr = smem_u32(Bs + (wn + nj2*16 + (lane&7) + ((lane>>4)<<3))*LDH + k0 + ((lane>>3)&1)*8);
                ldsm4(bfr, baddr);
                mma16816(acc[nj2*2],   afr, bfr);
                mma16816(acc[nj2*2+1], afr, bfr+2);
            }
        }
        __syncthreads();   // all warps done reading this buffer

        // issue prefetch for tile nt+2 into the buffer just freed
        if (nt + 2 < 9) {
            const __half* wsrc = g_wh + (nt+2)*64*192;
            unsigned bbase = smem_u32((char*)sh_qkv + 51200 + (nt & 1)*25600);
            #pragma unroll
            for (int it = 0; it < 3; it++) {
                int i   = tid + it*512;
                int row = i / 24;
                int cc  = (i % 24) * 8;
                cpa16(bbase + row*(LDH*2) + cc*2, wsrc + row*192 + cc);
            }
        }
        CPA_COMMIT();   // commit (possibly empty) to keep group counts aligned

        __half* obuf = g_v;
        if (nt < 3) { obuf = g_q; }
        else if (nt < 6) { obuf = g_k; }
        const int c0 = (nt % 3) * 64;
        const float* bp = bqkv + nt*64;

        #pragma unroll
        for (int rh = 0; rh < 2; rh++) {
            int tok = t0 + wm + grp + rh*8;
            __half* orow = obuf + win*WIN_ELEMS + tok*192 + c0;
            #pragma unroll
            for (int nj = 0; nj < 4; nj++) {
                int cl = wn + nj*8 + t2;
                float v0 = acc[nj][rh*2+0] + bp[cl];
                float v1 = acc[nj][rh*2+1] + bp[cl+1];
                *(__half2*)(orow + cl) = __floats2half2_rn(v0, v1);
            }
        }
    }

    // fused LePE: conv3x3 on this CTA's 96 flat channel images
    __syncthreads();
    __half* vflat = As;
    const __half* vsrc = g_v + win*WIN_ELEMS + t0*192;
    #pragma unroll
    for (int it = 0; it < 6; it++) {
        int i = tid + it*512;
        ((uint4*)vflat)[i] = ((const uint4*)vsrc)[i];
    }
    __syncthreads();

    __half* ldst = g_lepe + win*WIN_ELEMS + t0*192;
    #pragma unroll
    for (int it = 0; it < 48; it++) {
        int f  = tid + it*512;
        int ci = f >> 8;
        int p  = f & 255;
        int iy = p >> 4;
        int ix = p & 15;
        float s = s_bpe[ci];
        const float* wv = s_wpe + ci*9;
        const __half* img = vflat + ci*256;
        #pragma unroll
        for (int dy = -1; dy <= 1; dy++) {
            #pragma unroll
            for (int dx = -1; dx <= 1; dx++) {
                int jy = iy + dy;
                int jx = ix + dx;
                if (jy >= 0 && jy < 16 && jx >= 0 && jx < 16) {
                    s += __half2float(img[jy*16 + jx]) * wv[(dy+1)*3 + (dx+1)];
                }
            }
        }
        ldst[f] = __float2half(s);
    }
}

// ---------------------------------------------------------------------------
// K3: fused attention + output projection (HMMA). CTA = 128 q rows, 512 thr.
// 1 CTA/SM (reg-bound) -> use big smem + cp.async pipelining.
// smem: Qs[0,51200) Kfull[51200,153600)
//       Ps[0,67584) (overlays Q/K after S)  Wt0/1[67584,144384) (dead K)
//       Vbuf dbl [153600,204800)  s_max[204800) s_sum[206848) total 208896
// Commit groups: C1=QK C2=V0 C3=V1 C4=Wt C5=V2 C6=V3.
// ---------------------------------------------------------------------------
__global__ __launch_bounds__(512) void attn_kernel(const float* __restrict__ bout, float* __restrict__ out)
{
    extern __shared__ char sh_attn[];
    __half* Qs    = (__half*)sh_attn;
    __half* Kfull = (__half*)(sh_attn + 51200);
    __half* Ps    = (__half*)sh_attn;
    __half* O_s   = (__half*)sh_attn;
    float*  s_max = (float*)(sh_attn + 204800);
    float*  s_sum = (float*)(sh_attn + 206848);

    const int tid  = threadIdx.x;
    const int warp = tid >> 5;
    const int lane = tid & 31;
    const int win  = blockIdx.x >> 1;
    const int t0   = (blockIdx.x & 1) * 128;
    const int grp  = lane >> 2;
    const int t2   = (lane & 3) * 2;

    const __half* qg = g_q + win*WIN_ELEMS + t0*192;
    const __half* kg = g_k + win*WIN_ELEMS;
    const __half* vg = g_v + win*WIN_ELEMS;

    // C1: Q (128 rows) + K (256 rows)
    #pragma unroll
    for (int it = 0; it < 6; it++) {
        int i   = tid + it*512;
        int row = i / 24;
        int cc  = (i % 24) * 8;
        cpa16(smem_u32(Qs + row*LDH + cc), qg + row*192 + cc);
    }
    #pragma unroll
    for (int it = 0; it < 12; it++) {
        int i   = tid + it*512;
        int row = i / 24;
        int cc  = (i % 24) * 8;
        cpa16(smem_u32(Kfull + row*LDH + cc), kg + row*192 + cc);
    }
    CPA_COMMIT();

    // C2, C3: V chunks 0,1 (64 rows each) into double buffers
    #pragma unroll
    for (int vc0 = 0; vc0 < 2; vc0++) {
        unsigned vb = smem_u32(sh_attn + 153600 + vc0*25600);
        #pragma unroll
        for (int it = 0; it < 3; it++) {
            int i   = tid + it*512;
            int row = i / 24;
            int cc  = (i % 24) * 8;
            cpa16(vb + row*(LDH*2) + cc*2, vg + (vc0*64+row)*192 + cc);
        }
        CPA_COMMIT();
    }

    CPA_WAIT(2);        // C1 (Q+K) done; V0/V1 may still be in flight
    __syncthreads();

    // ---- S = Q K^T full 256 cols; warp grid 4M x 4N (tile 32x64) ----
    const int swm = (warp >> 2) * 32;
    const int swn = (warp & 3) * 64;
    float acc[2][8][4];
    for (int i = 0; i < 2; i++) {
        for (int j = 0; j < 8; j++) {
            for (int q = 0; q < 4; q++) { acc[i][j][q] = 0.f; }
        }
    }

    #pragma unroll
    for (int k0 = 0; k0 < 192; k0 += 16) {
        unsigned afr[2][4];
        #pragma unroll
        for (int mi = 0; mi < 2; mi++) {
            unsigned aaddr = smem_u32(Qs + (swm + mi*16 + (lane&15))*LDH + k0 + (lane>>4)*8);
            ldsm4(afr[mi], aaddr);
        }
        #pragma unroll
        for (int nj2 = 0; nj2 < 4; nj2++) {
            unsigned bfr[4];
            unsigned baddr = smem_u32(Kfull + (swn + nj2*16 + (lane&7) + ((lane>>4)<<3))*LDH + k0 + ((lane>>3)&1)*8);
            ldsm4(bfr, baddr);
            #pragma unroll
            for (int mi = 0; mi < 2; mi++) {
                mma16816(acc[mi][nj2*2],   afr[mi], bfr);
                mma16816(acc[mi][nj2*2+1], afr[mi], bfr+2);
            }
        }
    }

    const float scale = 0.07216878364870323f;
    #pragma unroll
    for (int mi = 0; mi < 2; mi++) {
        #pragma unroll
        for (int nj = 0; nj < 8; nj++) {
            #pragma unroll
            for (int q = 0; q < 4; q++) {
                acc[mi][nj][q] *= scale;
            }
        }
    }

    // per-row max partials
    #pragma unroll
    for (int mi = 0; mi < 2; mi++) {
        #pragma unroll
        for (int rh = 0; rh < 2; rh++) {
            float m = -1e30f;
            #pragma unroll
            for (int nj = 0; nj < 8; nj++) {
                m = fmaxf(m, fmaxf(acc[mi][nj][rh*2], acc[mi][nj][rh*2+1]));
            }
            m = fmaxf(m, __shfl_xor_sync(0xffffffffu, m, 1));
            m = fmaxf(m, __shfl_xor_sync(0xffffffffu, m, 2));
            if ((lane & 3) == 0) {
                s_max[(swm + mi*16 + grp + rh*8)*4 + (warp & 3)] = m;
            }
        }
    }
    __syncthreads();    // K fully read; s_max visible

    // C4: prefetch BOTH wout tiles into dead K region (lands during PV)
    {
        #pragma unroll
        for (int it = 0; it < 9; it++) {
            int i = tid + it*512;
            if (i < 4608) {
                int tile = i / 2304;
                int r    = (i % 2304) / 24;
                int cc   = ((i % 2304) % 24) * 8;
                const __half* wsrc = g_wh + 110592 + tile*96*192;
                unsigned dst = smem_u32(sh_attn + 67584 + tile*38400 + r*(LDH*2) + cc*2);
                cpa16(dst, wsrc + r*192 + cc);
            }
        }
        CPA_COMMIT();
    }

    // exp (unnormalized) -> Ps, per-row sum partials
    #pragma unroll
    for (int mi = 0; mi < 2; mi++) {
        #pragma unroll
        for (int rh = 0; rh < 2; rh++) {
            int row = swm + mi*16 + grp + rh*8;
            float m01 = fmaxf(s_max[row*4+0], s_max[row*4+1]);
            float m23 = fmaxf(s_max[row*4+2], s_max[row*4+3]);
            float rmax = fmaxf(m01, m23);
            float s = 0.f;
            #pragma unroll
            for (int nj = 0; nj < 8; nj++) {
                float e0 = __expf(acc[mi][nj][rh*2+0] - rmax);
                float e1 = __expf(acc[mi][nj][rh*2+1] - rmax);
                s += e0 + e1;
                int col = swn + nj*8 + t2;
                *(__half2*)(Ps + row*LDP + col) = __floats2half2_rn(e0, e1);
            }
            s += __shfl_xor_sync(0xffffffffu, s, 1);
            s += __shfl_xor_sync(0xffffffffu, s, 2);
            if ((lane & 3) == 0) {
                s_sum[row*4 + (warp & 3)] = s;
            }
        }
    }

    // ---- O = P V over 4 V chunks of 64; warp grid 4M x 4N (tile 32x48) ----
    const int pwm = (warp >> 2) * 32;
    const int pwn = (warp & 3) * 48;
    float oacc[2][6][4];
    for (int i = 0; i < 2; i++) {
        for (int j = 0; j < 6; j++) {
            for (int q = 0; q < 4; q++) { oacc[i][j][q] = 0.f; }
        }
    }

    #pragma unroll
    for (int vc = 0; vc < 4; vc++) {
        if (vc == 0) { CPA_WAIT(2); }
        else if (vc == 1) { CPA_WAIT(2); }
        else if (vc == 2) { CPA_WAIT(1); }
        else { CPA_WAIT(0); }
        __syncthreads();   // V chunk visible to all; Ps visible (vc=0)

        const __half* Vb = (const __half*)(sh_attn + 153600 + (vc & 1)*25600);

        #pragma unroll
        for (int k0 = 0; k0 < 64; k0 += 16) {
            unsigned afr[2][4];
            #pragma unroll
            for (int mi = 0; mi < 2; mi++) {
                unsigned aaddr = smem_u32(Ps + (pwm + mi*16 + (lane&15))*LDP + vc*64 + k0 + (lane>>4)*8);
                ldsm4(afr[mi], aaddr);
            }
            #pragma unroll
            for (int nj2 = 0; nj2 < 3; nj2++) {
                unsigned bfr[4];
                unsigned baddr = smem_u32(Vb + (k0 + (lane&7) + ((lane>>3)&1)*8)*LDH + pwn + nj2*16 + (lane>>4)*8);
                ldsm4t(bfr, baddr);
                #pragma unroll
                for (int mi = 0; mi < 2; mi++) {
                    mma16816(oacc[mi][nj2*2],   afr[mi], bfr);
                    mma16816(oacc[mi][nj2*2+1], afr[mi], bfr+2);
                }
            }
        }
        __syncthreads();   // buffer free before refill

        if (vc + 2 < 4) {
            unsigned vb = smem_u32(sh_attn + 153600 + (vc & 1)*25600);
            #pragma unroll
            for (int it = 0; it < 3; it++) {
                int i   = tid + it*512;
                int row = i / 24;
                int cc  = (i % 24) * 8;
                cpa16(vb + row*(LDH*2) + cc*2, vg + ((vc+2)*64+row)*192 + cc);
            }
        }
        CPA_COMMIT();
    }

    // ---- write O = PV/rowsum + lepe into O_s (fp16, [128][LDH]) ----
    const __half* lw = g_lepe + win*WIN_ELEMS + t0*192;
    #pragma unroll
    for (int mi = 0; mi < 2; mi++) {
        #pragma unroll
        for (int rh = 0; rh < 2; rh++) {
            int rl = pwm + mi*16 + grp + rh*8;
            float tot = s_sum[rl*4+0] + s_sum[rl*4+1] + s_sum[rl*4+2] + s_sum[rl*4+3];
            float inv = 1.f / tot;
            #pragma unroll
            for (int nj = 0; nj < 6; nj++) {
                int c = pwn + nj*8 + t2;
                __half2 lh = *(const __half2*)(lw + rl*192 + c);
                float2 lp = __half22float2(lh);
                float v0 = oacc[mi][nj][rh*2+0]*inv + lp.x;
                float v1 = oacc[mi][nj][rh*2+1]*inv + lp.y;
                *(__half2*)(O_s + rl*LDH + c) = __floats2half2_rn(v0, v1);
            }
        }
    }
    __syncthreads();   // O_s visible; Wt (C4) already waited at vc>=2

    // ---- fused output projection: O_s @ wout, scatter to out ----
    const int jwm = (warp >> 1) * 16;
    const int jwn = (warp & 1) * 48;
    const int bb = win >> 8;
    const int hy = (win >> 4) & 15;
    const int wx = win & 15;

    #pragma unroll
    for (int nt = 0; nt < 2; nt++) {
        const __half* Wt = (const __half*)(sh_attn + 67584 + nt*38400);

        float pacc[6][4];
        for (int j = 0; j < 6; j++) {
            for (int q = 0; q < 4; q++) { pacc[j][q] = 0.f; }
        }

        #pragma unroll
        for (int k0 = 0; k0 < 192; k0 += 16) {
            unsigned afr[4];
            unsigned aaddr = smem_u32(O_s + (jwm + (lane&15))*LDH + k0 + (lane>>4)*8);
            ldsm4(afr, aaddr);
            #pragma unroll
            for (int nj2 = 0; nj2 < 3; nj2++) {
                unsigned bfr[4];
                unsigned baddr = smem_u32(Wt + (jwn + nj2*16 + (lane&7) + ((lane>>4)<<3))*LDH + k0 + ((lane>>3)&1)*8);
                ldsm4(bfr, baddr);
                mma16816(pacc[nj2*2],   afr, bfr);
                mma16816(pacc[nj2*2+1], afr, bfr+2);
            }
        }

        #pragma unroll
        for (int rh = 0; rh < 2; rh++) {
            int t  = t0 + jwm + grp + rh*8;
            int ty = t >> 4;
            int tx = t & 15;
            int base = bb*12582912 + hy*786432 + ty*49152 + wx*3072 + tx*192;
            #pragma unroll
            for (int nj = 0; nj < 6; nj++) {
                int c = nt*96 + jwn + nj*8 + t2;
                float2 o2;
                o2.x = pacc[nj][rh*2+0] + bout[c];
                o2.y = pacc[nj][rh*2+1] + bout[c+1];
                *(float2*)(out + base + c) = o2;
            }
        }
    }
}

// ---------------------------------------------------------------------------
extern "C" void kernel_launch(void* const* d_in, const int* in_sizes, int n_in,
                              void* d_out, int out_size)
{
    const float* x    = (const float*)d_in[0];
    const float* wqkv = (const float*)d_in[1];
    const float* bqkv = (const float*)d_in[2];
    const float* wpe  = (const float*)d_in[3];
    const float* bpe  = (const float*)d_in[4];
    const float* wout = (const float*)d_in[5];
    const float* bout = (const float*)d_in[6];
    float* out = (float*)d_out;

    const int sm_qkv  = 106240;
    const int sm_attn = 208896;
    cudaFuncSetAttribute(qkv_kernel,  cudaFuncAttributeMaxDynamicSharedMemorySize, sm_qkv);
    cudaFuncSetAttribute(attn_kernel, cudaFuncAttributeMaxDynamicSharedMemorySize, sm_attn);

    convw_kernel<<<288, 256>>>(wqkv, wout);
    qkv_kernel <<<2048, 512, sm_qkv>>>(x, bqkv, wpe, bpe);
    attn_kernel<<<2048, 512, sm_attn>>>(bout, out);
}

// round 10
// speedup vs baseline: 1.3022x; 1.0344x over previous
#include <cuda_runtime.h>
#include <cuda_fp16.h>
#include <cstdint>

#define NW        1024
#define WIN_ELEMS (256*192)
#define LDH       200

__device__ __align__(16) __half g_q[NW*WIN_ELEMS];
__device__ __align__(16) __half g_k[NW*WIN_ELEMS];
__device__ __align__(16) __half g_v[NW*WIN_ELEMS];
__device__ __align__(16) __half g_lepe[NW*WIN_ELEMS];
__device__ __align__(16) __half g_wh[147456];   // fp16 wqkv (110592) then wout (36864)

__device__ __forceinline__ unsigned smem_u32(const void* ptr)
{
    return (unsigned)__cvta_generic_to_shared(ptr);
}

__device__ __forceinline__ void ldsm4(unsigned* r, unsigned a)
{
    asm volatile("ldmatrix.sync.aligned.m8n8.x4.shared.b16 {%0,%1,%2,%3}, [%4];" : "=r"(r[0]), "=r"(r[1]), "=r"(r[2]), "=r"(r[3]) : "r"(a));
}

__device__ __forceinline__ void ldsm4t(unsigned* r, unsigned a)
{
    asm volatile("ldmatrix.sync.aligned.m8n8.x4.trans.shared.b16 {%0,%1,%2,%3}, [%4];" : "=r"(r[0]), "=r"(r[1]), "=r"(r[2]), "=r"(r[3]) : "r"(a));
}

__device__ __forceinline__ void mma16816(float* d, const unsigned* a, const unsigned* b)
{
    asm volatile("mma.sync.aligned.m16n8k16.row.col.f32.f16.f16.f32 {%0,%1,%2,%3},{%4,%5,%6,%7},{%8,%9},{%0,%1,%2,%3};" : "+f"(d[0]), "+f"(d[1]), "+f"(d[2]), "+f"(d[3]) : "r"(a[0]), "r"(a[1]), "r"(a[2]), "r"(a[3]), "r"(b[0]), "r"(b[1]));
}

__device__ __forceinline__ void cpa16(unsigned dst, const void* src)
{
    asm volatile("cp.async.cg.shared.global [%0], [%1], 16;" :: "r"(dst), "l"(src));
}

#define CPA_COMMIT() asm volatile("cp.async.commit_group;")
#define CPA_WAIT(n)  asm volatile("cp.async.wait_group %0;" :: "n"(n))

// ---------------------------------------------------------------------------
// K0: one-shot weight conversion fp32 -> fp16 (wqkv then wout).
// ---------------------------------------------------------------------------
__global__ __launch_bounds__(256) void convw_kernel(const float* __restrict__ wqkv, const float* __restrict__ wout)
{
    int i = blockIdx.x*256 + threadIdx.x;
    if (i < 55296) {
        ((__half2*)g_wh)[i] = __floats2half2_rn(wqkv[2*i], wqkv[2*i+1]);
    } else if (i < 73728) {
        int j = i - 55296;
        ((__half2*)g_wh)[i] = __floats2half2_rn(wout[2*j], wout[2*j+1]);
    }
}

// ---------------------------------------------------------------------------
// K1: QKV projection (HMMA) + fused LePE tail. CTA = half window (128 rows).
// (unchanged from R9: cp.async double-buffered 64-col B tiles)
// ---------------------------------------------------------------------------
__global__ __launch_bounds__(512) void qkv_kernel(const float* __restrict__ x, const float* __restrict__ bqkv,
                                                  const float* __restrict__ wpe, const float* __restrict__ bpe)
{
    extern __shared__ __half sh_qkv[];
    __half* As    = sh_qkv;
    float*  s_wpe = (float*)((char*)sh_qkv + 102400);
    float*  s_bpe = s_wpe + 864;

    const int tid  = threadIdx.x;
    const int warp = tid >> 5;
    const int lane = tid & 31;
    const int hw   = blockIdx.x;
    const int win  = hw >> 1;
    const int t0   = (hw & 1) * 128;
    const int cbase= (hw & 1) * 96;
    const int bb   = win >> 8;
    const int hy   = (win >> 4) & 15;
    const int wx   = win & 15;
    const int winbase = bb*12582912 + hy*786432 + wx*3072;
    const int grp  = lane >> 2;
    const int t2   = (lane & 3) * 2;
    const int wm   = (warp >> 1) * 16;
    const int wn   = (warp & 1) * 32;

    #pragma unroll
    for (int bt = 0; bt < 2; bt++) {
        const __half* wsrc = g_wh + bt*64*192;
        unsigned bbase = smem_u32((char*)sh_qkv + 51200 + bt*25600);
        #pragma unroll
        for (int it = 0; it < 3; it++) {
            int i   = tid + it*512;
            int row = i / 24;
            int cc  = (i % 24) * 8;
            cpa16(bbase + row*(LDH*2) + cc*2, wsrc + row*192 + cc);
        }
        CPA_COMMIT();
    }

    #pragma unroll
    for (int it = 0; it < 2; it++) {
        int i = tid + it*512;
        if (i < 864) { s_wpe[i] = wpe[cbase*9 + i]; }
    }
    if (tid < 96) { s_bpe[tid] = bpe[cbase + tid]; }

    #pragma unroll
    for (int it = 0; it < 12; it++) {
        int i   = tid + it*512;
        int row = i / 48;
        int c   = (i % 48) * 4;
        int gtok = t0 + row;
        const float* src = x + winbase + (gtok>>4)*49152 + (gtok&15)*192 + c;
        float4 av = *(const float4*)src;
        __half2* dp = (__half2*)(As + row*LDH + c);
        dp[0] = __floats2half2_rn(av.x, av.y);
        dp[1] = __floats2half2_rn(av.z, av.w);
    }

    for (int nt = 0; nt < 9; nt++) {
        if (nt >= 7) { CPA_WAIT(0); } else { CPA_WAIT(1); }
        __syncthreads();

        const __half* Bs = (const __half*)((char*)sh_qkv + 51200 + (nt & 1)*25600);

        float acc[4][4];
        for (int j = 0; j < 4; j++) {
            for (int q = 0; q < 4; q++) { acc[j][q] = 0.f; }
        }

        #pragma unroll
        for (int k0 = 0; k0 < 192; k0 += 16) {
            unsigned afr[4];
            unsigned aaddr = smem_u32(As + (wm + (lane&15))*LDH + k0 + (lane>>4)*8);
            ldsm4(afr, aaddr);
            #pragma unroll
            for (int nj2 = 0; nj2 < 2; nj2++) {
                unsigned bfr[4];
                unsigned baddr = smem_u32(Bs + (wn + nj2*16 + (lane&7) + ((lane>>4)<<3))*LDH + k0 + ((lane>>3)&1)*8);
                ldsm4(bfr, baddr);
                mma16816(acc[nj2*2],   afr, bfr);
                mma16816(acc[nj2*2+1], afr, bfr+2);
            }
        }
        __syncthreads();

        if (nt + 2 < 9) {
            const __half* wsrc = g_wh + (nt+2)*64*192;
            unsigned bbase = smem_u32((char*)sh_qkv + 51200 + (nt & 1)*25600);
            #pragma unroll
            for (int it = 0; it < 3; it++) {
                int i   = tid + it*512;
                int row = i / 24;
                int cc  = (i % 24) * 8;
                cpa16(bbase + row*(LDH*2) + cc*2, wsrc + row*192 + cc);
            }
        }
        CPA_COMMIT();

        __half* obuf = g_v;
        if (nt < 3) { obuf = g_q; }
        else if (nt < 6) { obuf = g_k; }
        const int c0 = (nt % 3) * 64;
        const float* bp = bqkv + nt*64;

        #pragma unroll
        for (int rh = 0; rh < 2; rh++) {
            int tok = t0 + wm + grp + rh*8;
            __half* orow = obuf + win*WIN_ELEMS + tok*192 + c0;
            #pragma unroll
            for (int nj = 0; nj < 4; nj++) {
                int cl = wn + nj*8 + t2;
                float v0 = acc[nj][rh*2+0] + bp[cl];
                float v1 = acc[nj][rh*2+1] + bp[cl+1];
                *(__half2*)(orow + cl) = __floats2half2_rn(v0, v1);
            }
        }
    }

    __syncthreads();
    __half* vflat = As;
    const __half* vsrc = g_v + win*WIN_ELEMS + t0*192;
    #pragma unroll
    for (int it = 0; it < 6; it++) {
        int i = tid + it*512;
        ((uint4*)vflat)[i] = ((const uint4*)vsrc)[i];
    }
    __syncthreads();

    __half* ldst = g_lepe + win*WIN_ELEMS + t0*192;
    #pragma unroll
    for (int it = 0; it < 48; it++) {
        int f  = tid + it*512;
        int ci = f >> 8;
        int p  = f & 255;
        int iy = p >> 4;
        int ix = p & 15;
        float s = s_bpe[ci];
        const float* wv = s_wpe + ci*9;
        const __half* img = vflat + ci*256;
        #pragma unroll
        for (int dy = -1; dy <= 1; dy++) {
            #pragma unroll
            for (int dx = -1; dx <= 1; dx++) {
                int jy = iy + dy;
                int jx = ix + dx;
                if (jy >= 0 && jy < 16 && jx >= 0 && jx < 16) {
                    s += __half2float(img[jy*16 + jx]) * wv[(dy+1)*3 + (dx+1)];
                }
            }
        }
        ldst[f] = __float2half(s);
    }
}

// ---------------------------------------------------------------------------
// K3: register-resident fused attention + projection. 256 threads, 8 warps.
// Warp w owns q rows [w*16, w*16+16) x ALL 256 kv cols.
// S C-frags -> (softmax in regs, quad shuffles only) -> PV A-frags -> PV
// C-frags -> (inv + lepe) -> proj A-frags -> proj -> scatter. No smem for
// S/P/O; smem only Q,K,V(double buf 64 rows),Wt(overlay dead K).
// smem: Qs[0,51200) Kfull[51200,153600) Wt overlays[51200,128000)
//       Vbuf0[153600,179200) Vbuf1[179200,204800). total 204800.
// cp.async groups: C1=QK C2=V0 C3=V1 C4=Wt C5=V2 C6=V3.
// ---------------------------------------------------------------------------
__global__ __launch_bounds__(256) void attn_kernel(const float* __restrict__ bout, float* __restrict__ out)
{
    extern __shared__ char sh_attn[];
    __half* Qs    = (__half*)sh_attn;
    __half* Kfull = (__half*)(sh_attn + 51200);
    __half* Wt    = (__half*)(sh_attn + 51200);

    const int tid  = threadIdx.x;
    const int warp = tid >> 5;
    const int lane = tid & 31;
    const int win  = blockIdx.x >> 1;
    const int t0   = (blockIdx.x & 1) * 128;
    const int grp  = lane >> 2;
    const int t2   = (lane & 3) * 2;
    const int wm   = warp * 16;

    const __half* qg = g_q + win*WIN_ELEMS + t0*192;
    const __half* kg = g_k + win*WIN_ELEMS;
    const __half* vg = g_v + win*WIN_ELEMS;

    // C1: Q + K
    #pragma unroll
    for (int it = 0; it < 12; it++) {
        int i   = tid + it*256;
        int row = i / 24;
        int cc  = (i % 24) * 8;
        cpa16(smem_u32(Qs + row*LDH + cc), qg + row*192 + cc);
    }
    #pragma unroll
    for (int it = 0; it < 24; it++) {
        int i   = tid + it*256;
        int row = i / 24;
        int cc  = (i % 24) * 8;
        cpa16(smem_u32(Kfull + row*LDH + cc), kg + row*192 + cc);
    }
    CPA_COMMIT();

    // C2, C3: V chunks 0,1 (64 rows each)
    #pragma unroll
    for (int vc0 = 0; vc0 < 2; vc0++) {
        unsigned vb = smem_u32(sh_attn + 153600 + vc0*25600);
        #pragma unroll
        for (int it = 0; it < 6; it++) {
            int i   = tid + it*256;
            int row = i / 24;
            int cc  = (i % 24) * 8;
            cpa16(vb + row*(LDH*2) + cc*2, vg + (vc0*64+row)*192 + cc);
        }
        CPA_COMMIT();
    }

    CPA_WAIT(2);
    __syncthreads();

    // ---- Q fragments: 12 k-steps x 4 regs, held for whole S phase ----
    unsigned qa[48];
    #pragma unroll
    for (int ks = 0; ks < 12; ks++) {
        unsigned aaddr = smem_u32(Qs + (wm + (lane&15))*LDH + ks*16 + (lane>>4)*8);
        ldsm4(qa + ks*4, aaddr);
    }

    // ---- S = Q K^T : 32 n-tiles of 8 cols, acc in regs ----
    float acc[32][4];
    for (int j = 0; j < 32; j++) {
        for (int q = 0; q < 4; q++) { acc[j][q] = 0.f; }
    }

    #pragma unroll
    for (int ks = 0; ks < 12; ks++) {
        #pragma unroll
        for (int njp = 0; njp < 16; njp++) {
            unsigned bfr[4];
            unsigned baddr = smem_u32(Kfull + (njp*16 + (lane&7) + ((lane>>4)<<3))*LDH + ks*16 + ((lane>>3)&1)*8);
            ldsm4(bfr, baddr);
            mma16816(acc[njp*2],   qa + ks*4, bfr);
            mma16816(acc[njp*2+1], qa + ks*4, bfr+2);
        }
    }
    __syncthreads();   // K fully read by all warps

    // C4: prefetch BOTH wout tiles (192 rows) into dead K region
    #pragma unroll
    for (int it = 0; it < 18; it++) {
        int i   = tid + it*256;
        int row = i / 24;
        int cc  = (i % 24) * 8;
        cpa16(smem_u32(Wt + row*LDH + cc), g_wh + 110592 + row*192 + cc);
    }
    CPA_COMMIT();

    // ---- softmax entirely in registers (quad shuffles only) ----
    const float scale = 0.07216878364870323f;
    float mx0 = -1e30f;
    float mx1 = -1e30f;
    #pragma unroll
    for (int nj = 0; nj < 32; nj++) {
        acc[nj][0] *= scale; acc[nj][1] *= scale;
        acc[nj][2] *= scale; acc[nj][3] *= scale;
        mx0 = fmaxf(mx0, fmaxf(acc[nj][0], acc[nj][1]));
        mx1 = fmaxf(mx1, fmaxf(acc[nj][2], acc[nj][3]));
    }
    mx0 = fmaxf(mx0, __shfl_xor_sync(0xffffffffu, mx0, 1));
    mx0 = fmaxf(mx0, __shfl_xor_sync(0xffffffffu, mx0, 2));
    mx1 = fmaxf(mx1, __shfl_xor_sync(0xffffffffu, mx1, 1));
    mx1 = fmaxf(mx1, __shfl_xor_sync(0xffffffffu, mx1, 2));

    unsigned ph[64];   // P as PV A-fragments: ph[nj*2+0]=row grp, +1=row grp+8
    float sum0 = 0.f;
    float sum1 = 0.f;
    #pragma unroll
    for (int nj = 0; nj < 32; nj++) {
        float e0 = __expf(acc[nj][0] - mx0);
        float e1 = __expf(acc[nj][1] - mx0);
        float e2 = __expf(acc[nj][2] - mx1);
        float e3 = __expf(acc[nj][3] - mx1);
        sum0 += e0 + e1;
        sum1 += e2 + e3;
        __half2 h01 = __floats2half2_rn(e0, e1);
        __half2 h23 = __floats2half2_rn(e2, e3);
        ph[nj*2+0] = *(unsigned*)&h01;
        ph[nj*2+1] = *(unsigned*)&h23;
    }
    sum0 += __shfl_xor_sync(0xffffffffu, sum0, 1);
    sum0 += __shfl_xor_sync(0xffffffffu, sum0, 2);
    sum1 += __shfl_xor_sync(0xffffffffu, sum1, 1);
    sum1 += __shfl_xor_sync(0xffffffffu, sum1, 2);
    const float inv0 = 1.f / sum0;
    const float inv1 = 1.f / sum1;

    // ---- O = P V : P from regs (ph), V chunks of 64 double-buffered ----
    float oacc[24][4];
    for (int j = 0; j < 24; j++) {
        for (int q = 0; q < 4; q++) { oacc[j][q] = 0.f; }
    }

    #pragma unroll
    for (int cc4 = 0; cc4 < 4; cc4++) {
        if (cc4 == 0) { CPA_WAIT(2); }
        else if (cc4 == 1) { CPA_WAIT(2); }
        else if (cc4 == 2) { CPA_WAIT(1); }
        else { CPA_WAIT(0); }
        __syncthreads();

        const __half* Vb = (const __half*)(sh_attn + 153600 + (cc4 & 1)*25600);

        #pragma unroll
        for (int kq = 0; kq < 4; kq++) {
            int kt = cc4*4 + kq;
            #pragma unroll
            for (int g12 = 0; g12 < 12; g12++) {
                unsigned bfr[4];
                unsigned baddr = smem_u32(Vb + (kq*16 + (lane&7) + ((lane>>3)&1)*8)*LDH + g12*16 + (lane>>4)*8);
                ldsm4t(bfr, baddr);
                mma16816(oacc[g12*2],   ph + 4*kt, bfr);
                mma16816(oacc[g12*2+1], ph + 4*kt, bfr+2);
            }
        }
        __syncthreads();

        if (cc4 < 2) {
            unsigned vb = smem_u32(sh_attn + 153600 + (cc4 & 1)*25600);
            #pragma unroll
            for (int it = 0; it < 6; it++) {
                int i   = tid + it*256;
                int row = i / 24;
                int cc  = (i % 24) * 8;
                cpa16(vb + row*(LDH*2) + cc*2, vg + ((cc4+2)*64+row)*192 + cc);
            }
            CPA_COMMIT();
        }
    }

    // ---- finalize O in regs: inv + lepe; repack as proj A-fragments ----
    const __half* lw = g_lepe + win*WIN_ELEMS + t0*192;
    unsigned oh[48];
    #pragma unroll
    for (int nj = 0; nj < 24; nj++) {
        int c = nj*8 + t2;
        __half2 l0 = *(const __half2*)(lw + (wm + grp)*192 + c);
        __half2 l1 = *(const __half2*)(lw + (wm + grp + 8)*192 + c);
        float2 lp0 = __half22float2(l0);
        float2 lp1 = __half22float2(l1);
        float v0 = oacc[nj][0]*inv0 + lp0.x;
        float v1 = oacc[nj][1]*inv0 + lp0.y;
        float v2 = oacc[nj][2]*inv1 + lp1.x;
        float v3 = oacc[nj][3]*inv1 + lp1.y;
        __half2 h01 = __floats2half2_rn(v0, v1);
        __half2 h23 = __floats2half2_rn(v2, v3);
        oh[nj*2+0] = *(unsigned*)&h01;
        oh[nj*2+1] = *(unsigned*)&h23;
    }

    // ---- fused projection: O (regs) @ wout (smem), scatter to out ----
    float pacc[24][4];
    for (int j = 0; j < 24; j++) {
        for (int q = 0; q < 4; q++) { pacc[j][q] = 0.f; }
    }

    #pragma unroll
    for (int ks = 0; ks < 12; ks++) {
        #pragma unroll
        for (int nj2 = 0; nj2 < 12; nj2++) {
            unsigned bfr[4];
            unsigned baddr = smem_u32(Wt + (nj2*16 + (lane&7) + ((lane>>4)<<3))*LDH + ks*16 + ((lane>>3)&1)*8);
            ldsm4(bfr, baddr);
            mma16816(pacc[nj2*2],   oh + 4*ks, bfr);
            mma16816(pacc[nj2*2+1], oh + 4*ks, bfr+2);
        }
    }

    const int bb = win >> 8;
    const int hy = (win >> 4) & 15;
    const int wx = win & 15;
    #pragma unroll
    for (int rh = 0; rh < 2; rh++) {
        int t  = t0 + wm + grp + rh*8;
        int ty = t >> 4;
        int tx = t & 15;
        int base = bb*12582912 + hy*786432 + ty*49152 + wx*3072 + tx*192;
        #pragma unroll
        for (int nj = 0; nj < 24; nj++) {
            int c = nj*8 + t2;
            float2 o2;
            o2.x = pacc[nj][rh*2+0] + bout[c];
            o2.y = pacc[nj][rh*2+1] + bout[c+1];
            *(float2*)(out + base + c) = o2;
        }
    }
}

// ---------------------------------------------------------------------------
extern "C" void kernel_launch(void* const* d_in, const int* in_sizes, int n_in,
                              void* d_out, int out_size)
{
    const float* x    = (const float*)d_in[0];
    const float* wqkv = (const float*)d_in[1];
    const float* bqkv = (const float*)d_in[2];
    const float* wpe  = (const float*)d_in[3];
    const float* bpe  = (const float*)d_in[4];
    const float* wout = (const float*)d_in[5];
    const float* bout = (const float*)d_in[6];
    float* out = (float*)d_out;

    const int sm_qkv  = 106240;
    const int sm_attn = 204800;
    cudaFuncSetAttribute(qkv_kernel,  cudaFuncAttributeMaxDynamicSharedMemorySize, sm_qkv);
    cudaFuncSetAttribute(attn_kernel, cudaFuncAttributeMaxDynamicSharedMemorySize, sm_attn);

    convw_kernel<<<288, 256>>>(wqkv, wout);
    qkv_kernel <<<2048, 512, sm_qkv>>>(x, bqkv, wpe, bpe);
    attn_kernel<<<2048, 256, sm_attn>>>(bout, out);
}

// round 11
// speedup vs baseline: 1.4185x; 1.0893x over previous
#include <cuda_runtime.h>
#include <cuda_fp16.h>
#include <cstdint>

#define NW        1024
#define WIN_ELEMS (256*192)
#define LDH       200

__device__ __align__(16) __half g_q[NW*WIN_ELEMS];
__device__ __align__(16) __half g_k[NW*WIN_ELEMS];
__device__ __align__(16) __half g_v[NW*WIN_ELEMS];
__device__ __align__(16) __half g_lepe[NW*WIN_ELEMS];
__device__ __align__(16) __half g_wh[147456];   // fp16 wqkv (110592) then wout (36864)

__device__ __forceinline__ unsigned smem_u32(const void* ptr)
{
    return (unsigned)__cvta_generic_to_shared(ptr);
}

__device__ __forceinline__ void ldsm4(unsigned* r, unsigned a)
{
    asm volatile("ldmatrix.sync.aligned.m8n8.x4.shared.b16 {%0,%1,%2,%3}, [%4];" : "=r"(r[0]), "=r"(r[1]), "=r"(r[2]), "=r"(r[3]) : "r"(a));
}

__device__ __forceinline__ void ldsm4t(unsigned* r, unsigned a)
{
    asm volatile("ldmatrix.sync.aligned.m8n8.x4.trans.shared.b16 {%0,%1,%2,%3}, [%4];" : "=r"(r[0]), "=r"(r[1]), "=r"(r[2]), "=r"(r[3]) : "r"(a));
}

__device__ __forceinline__ void mma16816(float* d, const unsigned* a, const unsigned* b)
{
    asm volatile("mma.sync.aligned.m16n8k16.row.col.f32.f16.f16.f32 {%0,%1,%2,%3},{%4,%5,%6,%7},{%8,%9},{%0,%1,%2,%3};" : "+f"(d[0]), "+f"(d[1]), "+f"(d[2]), "+f"(d[3]) : "r"(a[0]), "r"(a[1]), "r"(a[2]), "r"(a[3]), "r"(b[0]), "r"(b[1]));
}

__device__ __forceinline__ void cpa16(unsigned dst, const void* src)
{
    asm volatile("cp.async.cg.shared.global [%0], [%1], 16;" :: "r"(dst), "l"(src));
}

#define CPA_COMMIT() asm volatile("cp.async.commit_group;")
#define CPA_WAIT(n)  asm volatile("cp.async.wait_group %0;" :: "n"(n))

// ---------------------------------------------------------------------------
// K0: one-shot weight conversion fp32 -> fp16 (wqkv then wout).
// ---------------------------------------------------------------------------
__global__ __launch_bounds__(256) void convw_kernel(const float* __restrict__ wqkv, const float* __restrict__ wout)
{
    int i = blockIdx.x*256 + threadIdx.x;
    if (i < 55296) {
        ((__half2*)g_wh)[i] = __floats2half2_rn(wqkv[2*i], wqkv[2*i+1]);
    } else if (i < 73728) {
        int j = i - 55296;
        ((__half2*)g_wh)[i] = __floats2half2_rn(wout[2*j], wout[2*j+1]);
    }
}

// ---------------------------------------------------------------------------
// K1: QKV projection (HMMA) + fused LePE tail. CTA = half window (128 rows).
// 256 threads, 8 warps, warp tile 32x32 (grid 4M x 2N) -> B-fragment reuse
// across 2 m-tiles cuts CTA ldsm4/tile 576 -> 384.
// smem: As[0,51200) Bs0[51200,76800) Bs1[76800,102400) wpe/bpe[102400,106240)
// ---------------------------------------------------------------------------
__global__ __launch_bounds__(256) void qkv_kernel(const float* __restrict__ x, const float* __restrict__ bqkv,
                                                  const float* __restrict__ wpe, const float* __restrict__ bpe)
{
    extern __shared__ __half sh_qkv[];
    __half* As    = sh_qkv;
    float*  s_wpe = (float*)((char*)sh_qkv + 102400);
    float*  s_bpe = s_wpe + 864;

    const int tid  = threadIdx.x;
    const int warp = tid >> 5;
    const int lane = tid & 31;
    const int hw   = blockIdx.x;
    const int win  = hw >> 1;
    const int t0   = (hw & 1) * 128;
    const int cbase= (hw & 1) * 96;
    const int bb   = win >> 8;
    const int hy   = (win >> 4) & 15;
    const int wx   = win & 15;
    const int winbase = bb*12582912 + hy*786432 + wx*3072;
    const int grp  = lane >> 2;
    const int t2   = (lane & 3) * 2;
    const int wm   = (warp >> 1) * 32;   // 4 m-groups of 32 rows
    const int wn   = (warp & 1) * 32;    // 2 n-groups of 32 cols

    // prefetch B tiles 0,1 (64 cols each) via cp.async
    #pragma unroll
    for (int bt = 0; bt < 2; bt++) {
        const __half* wsrc = g_wh + bt*64*192;
        unsigned bbase = smem_u32((char*)sh_qkv + 51200 + bt*25600);
        #pragma unroll
        for (int it = 0; it < 6; it++) {
            int i   = tid + it*256;
            int row = i / 24;
            int cc  = (i % 24) * 8;
            cpa16(bbase + row*(LDH*2) + cc*2, wsrc + row*192 + cc);
        }
        CPA_COMMIT();
    }

    // lepe params
    #pragma unroll
    for (int it = 0; it < 4; it++) {
        int i = tid + it*256;
        if (i < 864) { s_wpe[i] = wpe[cbase*9 + i]; }
    }
    if (tid < 96) { s_bpe[tid] = bpe[cbase + tid]; }

    // gather + fp16 convert A (128 tokens x 192 ch)
    #pragma unroll
    for (int it = 0; it < 24; it++) {
        int i   = tid + it*256;
        int row = i / 48;
        int c   = (i % 48) * 4;
        int gtok = t0 + row;
        const float* src = x + winbase + (gtok>>4)*49152 + (gtok&15)*192 + c;
        float4 av = *(const float4*)src;
        __half2* dp = (__half2*)(As + row*LDH + c);
        dp[0] = __floats2half2_rn(av.x, av.y);
        dp[1] = __floats2half2_rn(av.z, av.w);
    }

    for (int nt = 0; nt < 9; nt++) {
        if (nt >= 7) { CPA_WAIT(0); } else { CPA_WAIT(1); }
        __syncthreads();

        const __half* Bs = (const __half*)((char*)sh_qkv + 51200 + (nt & 1)*25600);

        float acc[2][4][4];
        for (int i = 0; i < 2; i++) {
            for (int j = 0; j < 4; j++) {
                for (int q = 0; q < 4; q++) { acc[i][j][q] = 0.f; }
            }
        }

        #pragma unroll
        for (int k0 = 0; k0 < 192; k0 += 16) {
            unsigned afr[2][4];
            #pragma unroll
            for (int mi = 0; mi < 2; mi++) {
                unsigned aaddr = smem_u32(As + (wm + mi*16 + (lane&15))*LDH + k0 + (lane>>4)*8);
                ldsm4(afr[mi], aaddr);
            }
            #pragma unroll
            for (int nb = 0; nb < 2; nb++) {
                unsigned bfr[4];
                unsigned baddr = smem_u32(Bs + (wn + nb*16 + (lane&7) + ((lane>>4)<<3))*LDH + k0 + ((lane>>3)&1)*8);
                ldsm4(bfr, baddr);
                #pragma unroll
                for (int mi = 0; mi < 2; mi++) {
                    mma16816(acc[mi][nb*2],   afr[mi], bfr);
                    mma16816(acc[mi][nb*2+1], afr[mi], bfr+2);
                }
            }
        }
        __syncthreads();

        if (nt + 2 < 9) {
            const __half* wsrc = g_wh + (nt+2)*64*192;
            unsigned bbase = smem_u32((char*)sh_qkv + 51200 + (nt & 1)*25600);
            #pragma unroll
            for (int it = 0; it < 6; it++) {
                int i   = tid + it*256;
                int row = i / 24;
                int cc  = (i % 24) * 8;
                cpa16(bbase + row*(LDH*2) + cc*2, wsrc + row*192 + cc);
            }
        }
        CPA_COMMIT();

        __half* obuf = g_v;
        if (nt < 3) { obuf = g_q; }
        else if (nt < 6) { obuf = g_k; }
        const int c0 = (nt % 3) * 64;
        const float* bp = bqkv + nt*64;

        #pragma unroll
        for (int mi = 0; mi < 2; mi++) {
            #pragma unroll
            for (int rh = 0; rh < 2; rh++) {
                int tok = t0 + wm + mi*16 + grp + rh*8;
                __half* orow = obuf + win*WIN_ELEMS + tok*192 + c0;
                #pragma unroll
                for (int nj = 0; nj < 4; nj++) {
                    int cl = wn + nj*8 + t2;
                    float v0 = acc[mi][nj][rh*2+0] + bp[cl];
                    float v1 = acc[mi][nj][rh*2+1] + bp[cl+1];
                    *(__half2*)(orow + cl) = __floats2half2_rn(v0, v1);
                }
            }
        }
    }

    // fused LePE: conv3x3 on this CTA's 96 flat channel images
    __syncthreads();
    __half* vflat = As;
    const __half* vsrc = g_v + win*WIN_ELEMS + t0*192;
    #pragma unroll
    for (int it = 0; it < 12; it++) {
        int i = tid + it*256;
        ((uint4*)vflat)[i] = ((const uint4*)vsrc)[i];
    }
    __syncthreads();

    __half* ldst = g_lepe + win*WIN_ELEMS + t0*192;
    #pragma unroll 4
    for (int it = 0; it < 96; it++) {
        int f  = tid + it*256;
        int ci = f >> 8;
        int p  = f & 255;
        int iy = p >> 4;
        int ix = p & 15;
        float s = s_bpe[ci];
        const float* wv = s_wpe + ci*9;
        const __half* img = vflat + ci*256;
        #pragma unroll
        for (int dy = -1; dy <= 1; dy++) {
            #pragma unroll
            for (int dx = -1; dx <= 1; dx++) {
                int jy = iy + dy;
                int jx = ix + dx;
                if (jy >= 0 && jy < 16 && jx >= 0 && jx < 16) {
                    s += __half2float(img[jy*16 + jx]) * wv[(dy+1)*3 + (dx+1)];
                }
            }
        }
        ldst[f] = __float2half(s);
    }
}

// ---------------------------------------------------------------------------
// K3: register-resident fused attention + projection. 256 threads, 8 warps.
// (unchanged from R10)
// ---------------------------------------------------------------------------
__global__ __launch_bounds__(256) void attn_kernel(const float* __restrict__ bout, float* __restrict__ out)
{
    extern __shared__ char sh_attn[];
    __half* Qs    = (__half*)sh_attn;
    __half* Kfull = (__half*)(sh_attn + 51200);
    __half* Wt    = (__half*)(sh_attn + 51200);

    const int tid  = threadIdx.x;
    const int warp = tid >> 5;
    const int lane = tid & 31;
    const int win  = blockIdx.x >> 1;
    const int t0   = (blockIdx.x & 1) * 128;
    const int grp  = lane >> 2;
    const int t2   = (lane & 3) * 2;
    const int wm   = warp * 16;

    const __half* qg = g_q + win*WIN_ELEMS + t0*192;
    const __half* kg = g_k + win*WIN_ELEMS;
    const __half* vg = g_v + win*WIN_ELEMS;

    #pragma unroll
    for (int it = 0; it < 12; it++) {
        int i   = tid + it*256;
        int row = i / 24;
        int cc  = (i % 24) * 8;
        cpa16(smem_u32(Qs + row*LDH + cc), qg + row*192 + cc);
    }
    #pragma unroll
    for (int it = 0; it < 24; it++) {
        int i   = tid + it*256;
        int row = i / 24;
        int cc  = (i % 24) * 8;
        cpa16(smem_u32(Kfull + row*LDH + cc), kg + row*192 + cc);
    }
    CPA_COMMIT();

    #pragma unroll
    for (int vc0 = 0; vc0 < 2; vc0++) {
        unsigned vb = smem_u32(sh_attn + 153600 + vc0*25600);
        #pragma unroll
        for (int it = 0; it < 6; it++) {
            int i   = tid + it*256;
            int row = i / 24;
            int cc  = (i % 24) * 8;
            cpa16(vb + row*(LDH*2) + cc*2, vg + (vc0*64+row)*192 + cc);
        }
        CPA_COMMIT();
    }

    CPA_WAIT(2);
    __syncthreads();

    unsigned qa[48];
    #pragma unroll
    for (int ks = 0; ks < 12; ks++) {
        unsigned aaddr = smem_u32(Qs + (wm + (lane&15))*LDH + ks*16 + (lane>>4)*8);
        ldsm4(qa + ks*4, aaddr);
    }

    float acc[32][4];
    for (int j = 0; j < 32; j++) {
        for (int q = 0; q < 4; q++) { acc[j][q] = 0.f; }
    }

    #pragma unroll
    for (int ks = 0; ks < 12; ks++) {
        #pragma unroll
        for (int njp = 0; njp < 16; njp++) {
            unsigned bfr[4];
            unsigned baddr = smem_u32(Kfull + (njp*16 + (lane&7) + ((lane>>4)<<3))*LDH + ks*16 + ((lane>>3)&1)*8);
            ldsm4(bfr, baddr);
            mma16816(acc[njp*2],   qa + ks*4, bfr);
            mma16816(acc[njp*2+1], qa + ks*4, bfr+2);
        }
    }
    __syncthreads();

    #pragma unroll
    for (int it = 0; it < 18; it++) {
        int i   = tid + it*256;
        int row = i / 24;
        int cc  = (i % 24) * 8;
        cpa16(smem_u32(Wt + row*LDH + cc), g_wh + 110592 + row*192 + cc);
    }
    CPA_COMMIT();

    const float scale = 0.07216878364870323f;
    float mx0 = -1e30f;
    float mx1 = -1e30f;
    #pragma unroll
    for (int nj = 0; nj < 32; nj++) {
        acc[nj][0] *= scale; acc[nj][1] *= scale;
        acc[nj][2] *= scale; acc[nj][3] *= scale;
        mx0 = fmaxf(mx0, fmaxf(acc[nj][0], acc[nj][1]));
        mx1 = fmaxf(mx1, fmaxf(acc[nj][2], acc[nj][3]));
    }
    mx0 = fmaxf(mx0, __shfl_xor_sync(0xffffffffu, mx0, 1));
    mx0 = fmaxf(mx0, __shfl_xor_sync(0xffffffffu, mx0, 2));
    mx1 = fmaxf(mx1, __shfl_xor_sync(0xffffffffu, mx1, 1));
    mx1 = fmaxf(mx1, __shfl_xor_sync(0xffffffffu, mx1, 2));

    unsigned ph[64];
    float sum0 = 0.f;
    float sum1 = 0.f;
    #pragma unroll
    for (int nj = 0; nj < 32; nj++) {
        float e0 = __expf(acc[nj][0] - mx0);
        float e1 = __expf(acc[nj][1] - mx0);
        float e2 = __expf(acc[nj][2] - mx1);
        float e3 = __expf(acc[nj][3] - mx1);
        sum0 += e0 + e1;
        sum1 += e2 + e3;
        __half2 h01 = __floats2half2_rn(e0, e1);
        __half2 h23 = __floats2half2_rn(e2, e3);
        ph[nj*2+0] = *(unsigned*)&h01;
        ph[nj*2+1] = *(unsigned*)&h23;
    }
    sum0 += __shfl_xor_sync(0xffffffffu, sum0, 1);
    sum0 += __shfl_xor_sync(0xffffffffu, sum0, 2);
    sum1 += __shfl_xor_sync(0xffffffffu, sum1, 1);
    sum1 += __shfl_xor_sync(0xffffffffu, sum1, 2);
    const float inv0 = 1.f / sum0;
    const float inv1 = 1.f / sum1;

    float oacc[24][4];
    for (int j = 0; j < 24; j++) {
        for (int q = 0; q < 4; q++) { oacc[j][q] = 0.f; }
    }

    #pragma unroll
    for (int cc4 = 0; cc4 < 4; cc4++) {
        if (cc4 == 0) { CPA_WAIT(2); }
        else if (cc4 == 1) { CPA_WAIT(2); }
        else if (cc4 == 2) { CPA_WAIT(1); }
        else { CPA_WAIT(0); }
        __syncthreads();

        const __half* Vb = (const __half*)(sh_attn + 153600 + (cc4 & 1)*25600);

        #pragma unroll
        for (int kq = 0; kq < 4; kq++) {
            int kt = cc4*4 + kq;
            #pragma unroll
            for (int g12 = 0; g12 < 12; g12++) {
                unsigned bfr[4];
                unsigned baddr = smem_u32(Vb + (kq*16 + (lane&7) + ((lane>>3)&1)*8)*LDH + g12*16 + (lane>>4)*8);
                ldsm4t(bfr, baddr);
                mma16816(oacc[g12*2],   ph + 4*kt, bfr);
                mma16816(oacc[g12*2+1], ph + 4*kt, bfr+2);
            }
        }
        __syncthreads();

        if (cc4 < 2) {
            unsigned vb = smem_u32(sh_attn + 153600 + (cc4 & 1)*25600);
            #pragma unroll
            for (int it = 0; it < 6; it++) {
                int i   = tid + it*256;
                int row = i / 24;
                int cc  = (i % 24) * 8;
                cpa16(vb + row*(LDH*2) + cc*2, vg + ((cc4+2)*64+row)*192 + cc);
            }
            CPA_COMMIT();
        }
    }

    const __half* lw = g_lepe + win*WIN_ELEMS + t0*192;
    unsigned oh[48];
    #pragma unroll
    for (int nj = 0; nj < 24; nj++) {
        int c = nj*8 + t2;
        __half2 l0 = *(const __half2*)(lw + (wm + grp)*192 + c);
        __half2 l1 = *(const __half2*)(lw + (wm + grp + 8)*192 + c);
        float2 lp0 = __half22float2(l0);
        float2 lp1 = __half22float2(l1);
        float v0 = oacc[nj][0]*inv0 + lp0.x;
        float v1 = oacc[nj][1]*inv0 + lp0.y;
        float v2 = oacc[nj][2]*inv1 + lp1.x;
        float v3 = oacc[nj][3]*inv1 + lp1.y;
        __half2 h01 = __floats2half2_rn(v0, v1);
        __half2 h23 = __floats2half2_rn(v2, v3);
        oh[nj*2+0] = *(unsigned*)&h01;
        oh[nj*2+1] = *(unsigned*)&h23;
    }

    float pacc[24][4];
    for (int j = 0; j < 24; j++) {
        for (int q = 0; q < 4; q++) { pacc[j][q] = 0.f; }
    }

    #pragma unroll
    for (int ks = 0; ks < 12; ks++) {
        #pragma unroll
        for (int nj2 = 0; nj2 < 12; nj2++) {
            unsigned bfr[4];
            unsigned baddr = smem_u32(Wt + (nj2*16 + (lane&7) + ((lane>>4)<<3))*LDH + ks*16 + ((lane>>3)&1)*8);
            ldsm4(bfr, baddr);
            mma16816(pacc[nj2*2],   oh + 4*ks, bfr);
            mma16816(pacc[nj2*2+1], oh + 4*ks, bfr+2);
        }
    }

    const int bb = win >> 8;
    const int hy = (win >> 4) & 15;
    const int wx = win & 15;
    #pragma unroll
    for (int rh = 0; rh < 2; rh++) {
        int t  = t0 + wm + grp + rh*8;
        int ty = t >> 4;
        int tx = t & 15;
        int base = bb*12582912 + hy*786432 + ty*49152 + wx*3072 + tx*192;
        #pragma unroll
        for (int nj = 0; nj < 24; nj++) {
            int c = nj*8 + t2;
            float2 o2;
            o2.x = pacc[nj][rh*2+0] + bout[c];
            o2.y = pacc[nj][rh*2+1] + bout[c+1];
            *(float2*)(out + base + c) = o2;
        }
    }
}

// ---------------------------------------------------------------------------
extern "C" void kernel_launch(void* const* d_in, const int* in_sizes, int n_in,
                              void* d_out, int out_size)
{
    const float* x    = (const float*)d_in[0];
    const float* wqkv = (const float*)d_in[1];
    const float* bqkv = (const float*)d_in[2];
    const float* wpe  = (const float*)d_in[3];
    const float* bpe  = (const float*)d_in[4];
    const float* wout = (const float*)d_in[5];
    const float* bout = (const float*)d_in[6];
    float* out = (float*)d_out;

    const int sm_qkv  = 106240;
    const int sm_attn = 204800;
    cudaFuncSetAttribute(qkv_kernel,  cudaFuncAttributeMaxDynamicSharedMemorySize, sm_qkv);
    cudaFuncSetAttribute(attn_kernel, cudaFuncAttributeMaxDynamicSharedMemorySize, sm_attn);

    convw_kernel<<<288, 256>>>(wqkv, wout);
    qkv_kernel <<<2048, 256, sm_qkv>>>(x, bqkv, wpe, bpe);
    attn_kernel<<<2048, 256, sm_attn>>>(bout, out);
}